// round 7
// baseline (speedup 1.0000x reference)
#include <cuda_runtime.h>
#include <cuda_bf16.h>
#include <math.h>
#include <stdint.h>
#include <stddef.h>

// ---------------- problem dims (fixed) ----------------
#define BB   8
#define LL   2048
#define CIN  32
#define DMODEL 512
#define DFF  2048
#define NH   8
#define HD   64
#define NE   2
#define UU   24
#define MROWS (BB*LL)      // 16384

// converted-weight layout (bf16 element offsets)
#define QKV_PER_LAYER (1536*512)          // 786432
#define W1_OFF  1572864
#define W2_OFF  3670016
#define WTOT    5767168

// ---------------- scratch ----------------
__device__ float g_xln [MROWS*CIN];
__device__ float g_h   [(size_t)MROWS*DMODEL];
__device__ float g_qkv [(size_t)MROWS*1536];
__device__ float g_M   [BB*NH*LL];
__device__ int   g_samp[LL*UU];
__device__ int   g_idxtop[BB*NH*UU];
__device__ float g_vmean[BB*NH*HD];
__device__ float g_upd [BB*NH*UU*HD];
__device__ float g_last[BB*DMODEL];
__device__ float g_pe  [LL*DMODEL];
__device__ float g_sc  [(size_t)BB*NH*UU*LL];
__device__ float g_baseo[BB*DMODEL];
__device__ __nv_bfloat16 g_aHi[(size_t)MROWS*DMODEL];
__device__ __nv_bfloat16 g_aLo[(size_t)MROWS*DMODEL];
__device__ __nv_bfloat16 g_fHi[(size_t)MROWS*DFF];
__device__ __nv_bfloat16 g_fLo[(size_t)MROWS*DFF];
__device__ __nv_bfloat16 g_wbHi[WTOT];
__device__ __nv_bfloat16 g_wbLo[WTOT];

// ================= helpers =================
__device__ __forceinline__ uint32_t packbf(__nv_bfloat16 a, __nv_bfloat16 b) {
    __nv_bfloat162 t = __halves2bfloat162(a, b);
    return *reinterpret_cast<uint32_t*>(&t);
}
__device__ __forceinline__ void mma16816(float* c, const uint32_t* a, const uint32_t* b) {
    asm volatile(
        "mma.sync.aligned.m16n8k16.row.col.f32.bf16.bf16.f32 "
        "{%0,%1,%2,%3}, {%4,%5,%6,%7}, {%8,%9}, {%0,%1,%2,%3};"
        : "+f"(c[0]), "+f"(c[1]), "+f"(c[2]), "+f"(c[3])
        : "r"(a[0]), "r"(a[1]), "r"(a[2]), "r"(a[3]), "r"(b[0]), "r"(b[1]));
}
__device__ __forceinline__ void ldsm4(uint32_t& r0, uint32_t& r1, uint32_t& r2, uint32_t& r3,
                                      uint32_t addr) {
    asm volatile("ldmatrix.sync.aligned.m8n8.x4.shared.b16 {%0,%1,%2,%3}, [%4];"
                 : "=r"(r0), "=r"(r1), "=r"(r2), "=r"(r3) : "r"(addr));
}
#define CP_ASYNC16(dst, src) \
    asm volatile("cp.async.ca.shared.global [%0], [%1], 16;" :: "r"(dst), "l"(src))
#define CP_COMMIT() asm volatile("cp.async.commit_group;" ::: "memory")
#define CP_WAIT1()  asm volatile("cp.async.wait_group 1;" ::: "memory")
#define CP_WAIT0()  asm volatile("cp.async.wait_group 0;" ::: "memory")

// XOR-swizzled 64B-row tile
__device__ __forceinline__ void stage_tile(uint32_t dstBase, const __nv_bfloat16* src,
                                           int K, int k0, int tid) {
    int row = tid >> 2, c = tid & 3;
    #pragma unroll
    for (int i = 0; i < 2; i++) {
        int r = row + 64 * i;
        uint32_t doff = (uint32_t)(r * 64 + ((c ^ ((r >> 1) & 3)) << 4));
        CP_ASYNC16(dstBase + doff, src + (size_t)r * K + k0 + c * 8);
    }
}

// ================= pipelined bf16x3 tensor GEMM =================
// OUT=0: fp32 C (+bias,res,relu). OUT=1: bf16 hi/lo outputs (+bias,relu).
// SEGB=1: bias segmented per 512 columns across b0/b1/b2 (merged QKV).
template<int RELU, int RES, int OUT, int SEGB>
__global__ __launch_bounds__(256, 2)
void tgemm_kernel(const __nv_bfloat16* __restrict__ aHi, const __nv_bfloat16* __restrict__ aLo,
                  const __nv_bfloat16* __restrict__ bHi, const __nv_bfloat16* __restrict__ bLo,
                  const float* __restrict__ b0, const float* __restrict__ b1,
                  const float* __restrict__ b2,
                  const float* __restrict__ res, float* __restrict__ C,
                  __nv_bfloat16* __restrict__ outHi, __nv_bfloat16* __restrict__ outLo,
                  int M, int N, int K) {
    extern __shared__ char smem[];
    uint32_t sb = (uint32_t)__cvta_generic_to_shared(smem);

    int tid = threadIdx.x;
    int wid = tid >> 5, lane = tid & 31;
    int warpM = wid >> 2, warpN = wid & 3;        // 2 x 4
    int bn = blockIdx.x, bm = blockIdx.y;

    const __nv_bfloat16* Ah = aHi + (size_t)(bm * 128) * K;
    const __nv_bfloat16* Al = aLo + (size_t)(bm * 128) * K;
    const __nv_bfloat16* Bh = bHi + (size_t)(bn * 128) * K;
    const __nv_bfloat16* Bl = bLo + (size_t)(bn * 128) * K;

    float acc[4][4][4];
    #pragma unroll
    for (int mt = 0; mt < 4; mt++)
        #pragma unroll
        for (int nt = 0; nt < 4; nt++)
            #pragma unroll
            for (int e = 0; e < 4; e++) acc[mt][nt][e] = 0.f;

    int nchunks = K >> 5;
    {
        stage_tile(sb,         Ah, K, 0, tid);
        stage_tile(sb + 8192,  Al, K, 0, tid);
        stage_tile(sb + 16384, Bh, K, 0, tid);
        stage_tile(sb + 24576, Bl, K, 0, tid);
        CP_COMMIT();
    }
    for (int c = 0; c < nchunks; c++) {
        if (c + 1 < nchunks) {
            uint32_t s1 = sb + ((c + 1) & 1) * 32768;
            int k0 = (c + 1) * 32;
            stage_tile(s1,         Ah, K, k0, tid);
            stage_tile(s1 + 8192,  Al, K, k0, tid);
            stage_tile(s1 + 16384, Bh, K, k0, tid);
            stage_tile(s1 + 24576, Bl, K, k0, tid);
            CP_COMMIT();
            CP_WAIT1();
        } else {
            CP_WAIT0();
        }
        __syncthreads();

        uint32_t st = sb + (c & 1) * 32768;
        #pragma unroll
        for (int pass = 0; pass < 3; pass++) {
            uint32_t aB = st + ((pass == 2) ? 8192 : 0);
            uint32_t bB = st + 16384 + ((pass == 1) ? 8192 : 0);
            #pragma unroll
            for (int ks = 0; ks < 2; ks++) {
                int cidx = ks * 2 + (lane >> 4);
                uint32_t afr[4][4];
                #pragma unroll
                for (int mt = 0; mt < 4; mt++) {
                    int row = warpM * 64 + mt * 16 + (lane & 15);
                    uint32_t addr = aB + row * 64 + ((cidx ^ ((row >> 1) & 3)) << 4);
                    ldsm4(afr[mt][0], afr[mt][1], afr[mt][2], afr[mt][3], addr);
                }
                uint32_t bfr[4][2];
                #pragma unroll
                for (int p = 0; p < 2; p++) {
                    int row = warpN * 32 + p * 16 + (lane & 15);
                    uint32_t addr = bB + row * 64 + ((cidx ^ ((row >> 1) & 3)) << 4);
                    uint32_t r0, r1, r2, r3;
                    ldsm4(r0, r1, r2, r3, addr);
                    bfr[p*2][0] = r0; bfr[p*2+1][0] = r1;
                    bfr[p*2][1] = r2; bfr[p*2+1][1] = r3;
                }
                #pragma unroll
                for (int mt = 0; mt < 4; mt++)
                    #pragma unroll
                    for (int nt = 0; nt < 4; nt++)
                        mma16816(acc[mt][nt], afr[mt], bfr[nt]);
            }
        }
        __syncthreads();
    }

    #pragma unroll
    for (int mt = 0; mt < 4; mt++) {
        int r0 = bm * 128 + warpM * 64 + mt * 16 + (lane >> 2);
        #pragma unroll
        for (int nt = 0; nt < 4; nt++) {
            int cc = bn * 128 + warpN * 32 + nt * 8 + (lane & 3) * 2;
            const float* bp;
            int cb;
            if (SEGB) {
                int seg = cc >> 9;
                bp = (seg == 0) ? b0 : ((seg == 1) ? b1 : b2);
                cb = cc & 511;
            } else { bp = b0; cb = cc; }
            float2 bi = *(const float2*)(bp + cb);
            float2 o0 = make_float2(acc[mt][nt][0] + bi.x, acc[mt][nt][1] + bi.y);
            float2 o1 = make_float2(acc[mt][nt][2] + bi.x, acc[mt][nt][3] + bi.y);
            size_t g0 = (size_t)r0 * N + cc;
            size_t g1 = (size_t)(r0 + 8) * N + cc;
            if (RES) {
                float2 q0 = *(const float2*)(res + g0);
                float2 q1 = *(const float2*)(res + g1);
                o0.x += q0.x; o0.y += q0.y; o1.x += q1.x; o1.y += q1.y;
            }
            if (RELU) {
                o0.x = fmaxf(o0.x, 0.f); o0.y = fmaxf(o0.y, 0.f);
                o1.x = fmaxf(o1.x, 0.f); o1.y = fmaxf(o1.y, 0.f);
            }
            if (OUT == 0) {
                *(float2*)(C + g0) = o0;
                *(float2*)(C + g1) = o1;
            } else {
                __nv_bfloat16 h0 = __float2bfloat16(o0.x), h1 = __float2bfloat16(o0.y);
                __nv_bfloat16 h2 = __float2bfloat16(o1.x), h3 = __float2bfloat16(o1.y);
                *(uint32_t*)(outHi + g0) = packbf(h0, h1);
                *(uint32_t*)(outHi + g1) = packbf(h2, h3);
                *(uint32_t*)(outLo + g0) = packbf(
                    __float2bfloat16(o0.x - __bfloat162float(h0)),
                    __float2bfloat16(o0.y - __bfloat162float(h1)));
                *(uint32_t*)(outLo + g1) = packbf(
                    __float2bfloat16(o1.x - __bfloat162float(h2)),
                    __float2bfloat16(o1.y - __bfloat162float(h3)));
            }
        }
    }
}

// ---------------- all-weight hi/lo conversion (once) ----------------
__global__ void wconv_kernel(const float4* __restrict__ Wq, const float4* __restrict__ Wk,
                             const float4* __restrict__ Wv, const float4* __restrict__ W1,
                             const float4* __restrict__ W2) {
    int j = blockIdx.x * 256 + threadIdx.x;   // float4 index, total 1441792
    if (j >= 1441792) return;
    const float4* src;
    if (j < 393216) {
        int layer = j / 196608;
        int r = j - layer * 196608;
        int seg = r >> 16, off = r & 65535;
        const float4* base = (seg == 0) ? Wq : ((seg == 1) ? Wk : Wv);
        src = base + layer * 65536 + off;
    } else if (j < 917504) {
        src = W1 + (j - 393216);
    } else {
        src = W2 + (j - 917504);
    }
    float4 f = *src;
    __nv_bfloat16 h0 = __float2bfloat16(f.x), h1 = __float2bfloat16(f.y);
    __nv_bfloat16 h2 = __float2bfloat16(f.z), h3 = __float2bfloat16(f.w);
    ((uint2*)g_wbHi)[j] = make_uint2(packbf(h0, h1), packbf(h2, h3));
    ((uint2*)g_wbLo)[j] = make_uint2(
        packbf(__float2bfloat16(f.x - __bfloat162float(h0)),
               __float2bfloat16(f.y - __bfloat162float(h1))),
        packbf(__float2bfloat16(f.z - __bfloat162float(h2)),
               __float2bfloat16(f.w - __bfloat162float(h3))));
}

// ---------------- positional-embedding table (once) ----------------
__global__ void pe_kernel() {     // grid 256 (i2), 256 threads
    int i2 = blockIdx.x;
    double dv = exp(-(double)(2 * i2) * (9.210340371976184 / 512.0));
    const double TWO_PI = 6.283185307179586;
    const double INV2PI = 0.15915494309189535;
    for (int l = threadIdx.x; l < LL; l += 256) {
        double arg = (double)l * dv;
        double qd = rint(arg * INV2PI);
        double r = fma(-qd, TWO_PI, arg);
        float rf = (float)r;
        g_pe[l * DMODEL + 2 * i2]     = sinf(rf);
        g_pe[l * DMODEL + 2 * i2 + 1] = cosf(rf);
    }
}

// ---------------- threefry2x32 (JAX partitionable) ----------------
__device__ __forceinline__ void tf2x32(uint32_t k0, uint32_t k1,
                                       uint32_t x0, uint32_t x1,
                                       uint32_t& o0, uint32_t& o1) {
    uint32_t ks2 = k0 ^ k1 ^ 0x1BD11BDAu;
    uint32_t v0 = x0 + k0, v1 = x1 + k1;
#define TF_RND(r) { v0 += v1; v1 = (v1 << (r)) | (v1 >> (32 - (r))); v1 ^= v0; }
    TF_RND(13) TF_RND(15) TF_RND(26) TF_RND(6)   v0 += k1;  v1 += ks2 + 1u;
    TF_RND(17) TF_RND(29) TF_RND(16) TF_RND(24)  v0 += ks2; v1 += k0 + 2u;
    TF_RND(13) TF_RND(15) TF_RND(26) TF_RND(6)   v0 += k0;  v1 += k1 + 3u;
    TF_RND(17) TF_RND(29) TF_RND(16) TF_RND(24)  v0 += k1;  v1 += ks2 + 4u;
    TF_RND(13) TF_RND(15) TF_RND(26) TF_RND(6)   v0 += ks2; v1 += k0 + 5u;
#undef TF_RND
    o0 = v0; o1 = v1;
}

__global__ void sample_kernel(int layer) {
    int j = blockIdx.x * blockDim.x + threadIdx.x;
    if (j >= LL * UU) return;
    uint32_t a0, a1;
    tf2x32(0u, 42u, 0u, (uint32_t)layer, a0, a1);
    uint32_t k2a, k2b;
    tf2x32(a0, a1, 0u, 1u, k2a, k2b);
    uint32_t o0, o1;
    tf2x32(k2a, k2b, 0u, (uint32_t)j, o0, o1);
    g_samp[j] = (int)((o0 ^ o1) & 2047u);
}

// ---------------- input layernorm over C_IN=32 ----------------
__global__ void ln32_kernel(const float* __restrict__ x,
                            const float* __restrict__ g, const float* __restrict__ b) {
    int row  = blockIdx.x * 8 + (threadIdx.x >> 5);
    int lane = threadIdx.x & 31;
    float v = x[(size_t)row * CIN + lane];
    float s = v;
    #pragma unroll
    for (int o = 16; o; o >>= 1) s += __shfl_xor_sync(~0u, s, o);
    float m = s * (1.f / 32.f);
    float d = v - m;
    float ss = d * d;
    #pragma unroll
    for (int o = 16; o; o >>= 1) ss += __shfl_xor_sync(~0u, ss, o);
    float r = rsqrtf(ss * (1.f / 32.f) + 1e-5f);
    g_xln[(size_t)row * CIN + lane] = d * r * g[lane] + b[lane];
}

// ---------------- token conv + pe table + time proj ----------------
__global__ void embed_kernel(const float* __restrict__ tfeat,
                             const float* __restrict__ Wtok,
                             const float* __restrict__ Wtime,
                             const float* __restrict__ btime) {
    int bl = blockIdx.x;
    int l = bl & (LL - 1);
    int b = bl >> 11;
    __shared__ float xs[96];
    __shared__ float tf[4];
    int tid = threadIdx.x; // 128
    if (tid < 96) {
        int w = tid / 32, c = tid % 32;
        int lsrc = (l - 1 + w + LL) & (LL - 1);
        xs[tid] = g_xln[((size_t)b * LL + lsrc) * CIN + c];
    }
    if (tid < 4) tf[tid] = tfeat[((size_t)b * LL + l) * 4 + tid];
    __syncthreads();
    for (int m = tid; m < DMODEL; m += 128) {
        float acc = btime[m];
        #pragma unroll 8
        for (int wc = 0; wc < 96; wc++) acc += xs[wc] * Wtok[wc * DMODEL + m];
        #pragma unroll
        for (int t = 0; t < 4; t++) acc += tf[t] * Wtime[m * 4 + t];
        float v = acc + g_pe[l * DMODEL + m];
        size_t idx = ((size_t)b * LL + l) * DMODEL + m;
        g_h[idx] = v;
        __nv_bfloat16 hv = __float2bfloat16(v);
        g_aHi[idx] = hv;
        g_aLo[idx] = __float2bfloat16(v - __bfloat162float(hv));
    }
}

// ---------------- M scores ----------------
__global__ void mscore_kernel() {
    int wid  = (blockIdx.x * blockDim.x + threadIdx.x) >> 5;
    int lane = threadIdx.x & 31;
    if (wid >= BB * NH * LL) return;
    int l = wid & (LL - 1);
    int h = (wid >> 11) & (NH - 1);
    int b = wid >> 14;
    const float* qr = g_qkv + ((size_t)b * LL + l) * 1536 + h * 64;
    float q0 = qr[lane * 2], q1 = qr[lane * 2 + 1];
    float mx = -INFINITY, sm = 0.f;
    #pragma unroll 4
    for (int s = 0; s < UU; s++) {
        int ks = g_samp[l * UU + s];
        const float* kr = g_qkv + ((size_t)b * LL + ks) * 1536 + 512 + h * 64;
        float v = q0 * kr[lane * 2] + q1 * kr[lane * 2 + 1];
        #pragma unroll
        for (int o = 16; o; o >>= 1) v += __shfl_xor_sync(~0u, v, o);
        mx = fmaxf(mx, v);
        sm += v;
    }
    if (lane == 0)
        g_M[((size_t)(b * NH + h)) * LL + l] = mx - sm * (1.0f / (float)LL);
}

// ---------------- top-24 per (b,h), JAX tie semantics ----------------
__global__ void topk_kernel() {
    int bh = blockIdx.x;
    int tid = threadIdx.x;   // 256
    __shared__ float sv[LL];
    __shared__ float rv[256];
    __shared__ int   ri[256];
    for (int i = tid; i < LL; i += 256) sv[i] = g_M[(size_t)bh * LL + i];
    __syncthreads();
    for (int t = 0; t < UU; t++) {
        float bvv = -INFINITY; int bi = LL;
        for (int i = tid; i < LL; i += 256) {
            float v = sv[i];
            if (v > bvv || (v == bvv && i < bi)) { bvv = v; bi = i; }
        }
        rv[tid] = bvv; ri[tid] = bi;
        __syncthreads();
        for (int s = 128; s > 0; s >>= 1) {
            if (tid < s) {
                float v2 = rv[tid + s]; int i2 = ri[tid + s];
                if (v2 > rv[tid] || (v2 == rv[tid] && i2 < ri[tid])) { rv[tid] = v2; ri[tid] = i2; }
            }
            __syncthreads();
        }
        if (tid == 0) { g_idxtop[bh * UU + t] = ri[0]; sv[ri[0]] = -INFINITY; }
        __syncthreads();
    }
}

// ---------------- mean(V) over L ----------------
__global__ void vmean_kernel() {
    int bh = blockIdx.x;
    int h = bh & (NH - 1), b = bh >> 3;
    int tid = threadIdx.x;            // 256
    int d = tid & 63, part = tid >> 6;
    float s = 0.f;
    for (int l = part; l < LL; l += 4)
        s += g_qkv[((size_t)b * LL + l) * 1536 + 1024 + h * 64 + d];
    __shared__ float red[256];
    red[tid] = s; __syncthreads();
    if (tid < 64) {
        float tot = red[tid] + red[tid + 64] + red[tid + 128] + red[tid + 192];
        g_vmean[bh * HD + tid] = tot * (1.0f / (float)LL);
    }
}

// ---------------- scores for selected queries: g_sc[bh][u][k] ----------------
__global__ void qkscore_kernel() {   // grid (64, 8), 256 threads
    int bh = blockIdx.x;
    int kt = blockIdx.y;
    int h = bh & 7, b = bh >> 3;
    int tid = threadIdx.x;
    __shared__ float qs[UU * 64];
    __shared__ float sc[UU][256];
    size_t bL = (size_t)b * LL;
    for (int i = tid; i < UU * 64; i += 256) {
        int u = i >> 6, d = i & 63;
        qs[i] = g_qkv[(bL + g_idxtop[bh * UU + u]) * 1536 + h * 64 + d];
    }
    __syncthreads();
    int k = kt * 256 + tid;
    float4 kr[16];
    const float4* kp = (const float4*)(g_qkv + (bL + k) * 1536 + 512 + h * 64);
    #pragma unroll
    for (int i = 0; i < 16; i++) kr[i] = kp[i];
    #pragma unroll 4
    for (int u = 0; u < UU; u++) {
        const float4* qp = (const float4*)(qs + u * 64);
        float s = 0.f;
        #pragma unroll
        for (int i = 0; i < 16; i++) {
            float4 q4 = qp[i];
            s += q4.x * kr[i].x + q4.y * kr[i].y + q4.z * kr[i].z + q4.w * kr[i].w;
        }
        sc[u][tid] = s * 0.125f;
    }
    __syncthreads();
    for (int i = tid; i < UU * 256; i += 256) {
        int u = i >> 8, c = i & 255;
        g_sc[((size_t)bh * UU + u) * LL + kt * 256 + c] = sc[u][c];
    }
}

// ---------------- softmax + weighted V for selected queries ----------------
__global__ void attnupd_kernel() {
    int bid = blockIdx.x;            // bh*UU + u
    int u = bid % UU;
    int bh = bid / UU;
    int h = bh & (NH - 1), b = bh >> 3;
    int tid = threadIdx.x;           // 256
    __shared__ float p[LL];
    __shared__ float red[256];
    size_t bL = (size_t)b * LL;
    const float* sr = g_sc + ((size_t)bh * UU + u) * LL;
    float lmax = -INFINITY;
    for (int k = tid; k < LL; k += 256) {
        float s = sr[k];
        p[k] = s;
        lmax = fmaxf(lmax, s);
    }
    red[tid] = lmax; __syncthreads();
    for (int s = 128; s > 0; s >>= 1) { if (tid < s) red[tid] = fmaxf(red[tid], red[tid+s]); __syncthreads(); }
    float mx = red[0]; __syncthreads();
    float lsum = 0.f;
    for (int k = tid; k < LL; k += 256) { float e = expf(p[k] - mx); p[k] = e; lsum += e; }
    red[tid] = lsum; __syncthreads();
    for (int s = 128; s > 0; s >>= 1) { if (tid < s) red[tid] += red[tid+s]; __syncthreads(); }
    float S = red[0]; __syncthreads();
    int d = tid & 63, part = tid >> 6;
    float acc = 0.f;
    for (int k = part; k < LL; k += 4)
        acc += p[k] * g_qkv[(bL + k) * 1536 + 1024 + h * 64 + d];
    red[tid] = acc; __syncthreads();
    if (tid < 64) {
        float tot = red[tid] + red[tid + 64] + red[tid + 128] + red[tid + 192];
        g_upd[(size_t)bid * HD + tid] = tot / S;
    }
}

// ---------------- base O-projection: baseo[b][n] = vmeanvec[b].Wo[n] + bo[n] ------
__global__ void baseo_kernel(const float* __restrict__ Wo, const float* __restrict__ bo) {
    int b = blockIdx.x;        // 8
    int n = threadIdx.x;       // 512
    __shared__ float bv[512];
    bv[n] = g_vmean[b * 512 + n];
    __syncthreads();
    float acc = bo[n];
    const float* wr = Wo + (size_t)n * 512;
    #pragma unroll 8
    for (int k = 0; k < 512; k++) acc += bv[k] * wr[k];
    g_baseo[b * 512 + n] = acc;
}

// ---------------- broadcast add: h += baseo[b] ----------------
__global__ void bcast_kernel() {
    size_t j = (size_t)blockIdx.x * 256 + threadIdx.x;   // float4 index
    int b = (int)(j >> 18);                              // 2048*512/4 = 262144 f4 per batch
    int n4 = (int)(j & 127);
    float4 v = ((float4*)g_h)[j];
    float4 a = ((const float4*)g_baseo)[b * 128 + n4];
    v.x += a.x; v.y += a.y; v.z += a.z; v.w += a.w;
    ((float4*)g_h)[j] = v;
}

// ---------------- sparse delta O-projection ----------------
__global__ void deltao_kernel(const float* __restrict__ Wo) {
    int b = blockIdx.y;
    int n = blockIdx.x * 128 + threadIdx.x;   // grid.x = 4
    int tid = threadIdx.x;
    __shared__ float ds[UU * 64];
    for (int h = 0; h < NH; h++) {
        for (int i = tid; i < UU * 64; i += 128) {
            int u = i >> 6, d = i & 63;
            int gi = (b * NH + h) * UU + u;
            ds[i] = g_upd[(size_t)gi * 64 + d] - g_vmean[(b * NH + h) * 64 + d];
        }
        __syncthreads();
        const float* wr = Wo + (size_t)n * 512 + h * 64;
        for (int u = 0; u < UU; u++) {
            float c = 0.f;
            const float* dd = ds + u * 64;
            #pragma unroll 16
            for (int d = 0; d < 64; d++) c += dd[d] * wr[d];
            int l = g_idxtop[(b * NH + h) * UU + u];
            g_h[((size_t)b * LL + l) * 512 + n] += c;
        }
        __syncthreads();
    }
}

// ---------------- layernorm over 512 (optionally emits hi/lo) ----------------
__global__ void ln512_kernel(const float* __restrict__ in, float* __restrict__ out,
                             const float* __restrict__ g, const float* __restrict__ b,
                             size_t strideIn, size_t strideOut,
                             __nv_bfloat16* __restrict__ hiOut,
                             __nv_bfloat16* __restrict__ loOut) {
    int row = blockIdx.x;
    int tid = threadIdx.x;  // 128
    const float* x = in + (size_t)row * strideIn;
    float4 v = *(const float4*)(x + tid * 4);
    float s  = v.x + v.y + v.z + v.w;
    float ss = v.x*v.x + v.y*v.y + v.z*v.z + v.w*v.w;
    __shared__ float rs[4], rss[4];
    #pragma unroll
    for (int o = 16; o; o >>= 1) {
        s  += __shfl_xor_sync(~0u, s, o);
        ss += __shfl_xor_sync(~0u, ss, o);
    }
    int w = tid >> 5, lane = tid & 31;
    if (lane == 0) { rs[w] = s; rss[w] = ss; }
    __syncthreads();
    s  = rs[0] + rs[1] + rs[2] + rs[3];
    ss = rss[0] + rss[1] + rss[2] + rss[3];
    float m = s * (1.f / 512.f);
    float var = ss * (1.f / 512.f) - m * m;
    float r = rsqrtf(var + 1e-5f);
    float4 gg = *(const float4*)(g + tid * 4);
    float4 bb = *(const float4*)(b + tid * 4);
    float4 o4;
    o4.x = (v.x - m) * r * gg.x + bb.x;
    o4.y = (v.y - m) * r * gg.y + bb.y;
    o4.z = (v.z - m) * r * gg.z + bb.z;
    o4.w = (v.w - m) * r * gg.w + bb.w;
    *(float4*)(out + (size_t)row * strideOut + tid * 4) = o4;
    if (hiOut) {
        size_t e = (size_t)row * DMODEL + tid * 4;
        __nv_bfloat16 h0 = __float2bfloat16(o4.x), h1 = __float2bfloat16(o4.y);
        __nv_bfloat16 h2 = __float2bfloat16(o4.z), h3 = __float2bfloat16(o4.w);
        *(uint2*)(hiOut + e) = make_uint2(packbf(h0, h1), packbf(h2, h3));
        *(uint2*)(loOut + e) = make_uint2(
            packbf(__float2bfloat16(o4.x - __bfloat162float(h0)),
                   __float2bfloat16(o4.y - __bfloat162float(h1))),
            packbf(__float2bfloat16(o4.z - __bfloat162float(h2)),
                   __float2bfloat16(o4.w - __bfloat162float(h3))));
    }
}

// ---------------- final head ----------------
__global__ void head_kernel(const float* __restrict__ Wpre, const float* __restrict__ bpre,
                            const float* __restrict__ Wfc,  const float* __restrict__ bfc,
                            float* __restrict__ out) {
    int b = blockIdx.x;
    int tid = threadIdx.x;  // 256
    __shared__ float red[256];
    const float* x = g_last + (size_t)b * DMODEL;
    float acc = bpre[tid];
    const float* w = Wpre + (size_t)tid * DMODEL;
    #pragma unroll 8
    for (int k = 0; k < DMODEL; k++) acc += x[k] * w[k];
    float pre = fmaxf(acc, 0.f);
    red[tid] = pre * Wfc[tid];
    __syncthreads();
    for (int s = 128; s > 0; s >>= 1) { if (tid < s) red[tid] += red[tid + s]; __syncthreads(); }
    if (tid == 0) out[b] = red[0] + bfc[0];
}

// ---------------- host orchestration ----------------
#define SMEM_GEMM 65536

extern "C" void kernel_launch(void* const* d_in, const int* in_sizes, int n_in,
                              void* d_out, int out_size) {
    const float* x      = (const float*)d_in[0];
    const float* tfeat  = (const float*)d_in[1];
    const float* g_in   = (const float*)d_in[2];
    const float* b_in   = (const float*)d_in[3];
    const float* W_tok  = (const float*)d_in[4];
    const float* W_time = (const float*)d_in[5];
    const float* b_time = (const float*)d_in[6];
    const float* Wq     = (const float*)d_in[7];
    const float* bq     = (const float*)d_in[8];
    const float* Wk     = (const float*)d_in[9];
    const float* bk     = (const float*)d_in[10];
    const float* Wv     = (const float*)d_in[11];
    const float* bv     = (const float*)d_in[12];
    const float* Wo     = (const float*)d_in[13];
    const float* bo     = (const float*)d_in[14];
    const float* W1     = (const float*)d_in[15];
    const float* b1     = (const float*)d_in[16];
    const float* W2     = (const float*)d_in[17];
    const float* b2     = (const float*)d_in[18];
    const float* g1     = (const float*)d_in[19];
    const float* be1    = (const float*)d_in[20];
    const float* g2     = (const float*)d_in[21];
    const float* be2    = (const float*)d_in[22];
    const float* g_enc  = (const float*)d_in[23];
    const float* b_enc  = (const float*)d_in[24];
    const float* W_pre  = (const float*)d_in[25];
    const float* b_pre  = (const float*)d_in[26];
    const float* W_fc   = (const float*)d_in[27];
    const float* b_fc   = (const float*)d_in[28];

    float *h, *qkv, *last;
    __nv_bfloat16 *aHi, *aLo, *fHi, *fLo, *wbHi, *wbLo;
    cudaGetSymbolAddress((void**)&h,    g_h);
    cudaGetSymbolAddress((void**)&qkv,  g_qkv);
    cudaGetSymbolAddress((void**)&last, g_last);
    cudaGetSymbolAddress((void**)&aHi,  g_aHi);
    cudaGetSymbolAddress((void**)&aLo,  g_aLo);
    cudaGetSymbolAddress((void**)&fHi,  g_fHi);
    cudaGetSymbolAddress((void**)&fLo,  g_fLo);
    cudaGetSymbolAddress((void**)&wbHi, g_wbHi);
    cudaGetSymbolAddress((void**)&wbLo, g_wbLo);

    cudaFuncSetAttribute(tgemm_kernel<0,0,0,1>, cudaFuncAttributeMaxDynamicSharedMemorySize, SMEM_GEMM);
    cudaFuncSetAttribute(tgemm_kernel<1,0,1,0>, cudaFuncAttributeMaxDynamicSharedMemorySize, SMEM_GEMM);
    cudaFuncSetAttribute(tgemm_kernel<0,1,0,0>, cudaFuncAttributeMaxDynamicSharedMemorySize, SMEM_GEMM);

    pe_kernel<<<256, 256>>>();
    ln32_kernel<<<MROWS / 8, 256>>>(x, g_in, b_in);
    embed_kernel<<<MROWS, 128>>>(tfeat, W_tok, W_time, b_time);
    wconv_kernel<<<5632, 256>>>((const float4*)Wq, (const float4*)Wk, (const float4*)Wv,
                                (const float4*)W1, (const float4*)W2);

    dim3 gQKV(1536 / 128, MROWS / 128);   // (12,128)
    dim3 gF1(DFF / 128,  MROWS / 128);    // (16,128)
    dim3 gF2(DMODEL / 128, MROWS / 128);  // (4,128)

    for (int i = 0; i < NE; i++) {
        size_t wOff  = (size_t)i * DMODEL * DMODEL;
        size_t bOff  = (size_t)i * DMODEL;
        size_t b1Off = (size_t)i * DFF;
        size_t qkvW  = (size_t)i * QKV_PER_LAYER;
        size_t w1W   = W1_OFF + (size_t)i * DFF * DMODEL;
        size_t w2W   = W2_OFF + (size_t)i * DFF * DMODEL;

        sample_kernel<<<(LL * UU + 255) / 256, 256>>>(i);

        tgemm_kernel<0,0,0,1><<<gQKV, 256, SMEM_GEMM>>>(
            aHi, aLo, wbHi + qkvW, wbLo + qkvW,
            bq + bOff, bk + bOff, bv + bOff, nullptr, qkv, nullptr, nullptr,
            MROWS, 1536, DMODEL);

        mscore_kernel<<<(BB * NH * LL * 32) / 256, 256>>>();
        topk_kernel<<<BB * NH, 256>>>();
        vmean_kernel<<<BB * NH, 256>>>();
        qkscore_kernel<<<dim3(BB * NH, 8), 256>>>();
        attnupd_kernel<<<BB * NH * UU, 256>>>();
        baseo_kernel<<<BB, 512>>>(Wo + wOff, bo + bOff);
        bcast_kernel<<<(MROWS * DMODEL / 4) / 256, 256>>>();
        deltao_kernel<<<dim3(4, BB), 128>>>(Wo + wOff);
        ln512_kernel<<<MROWS, 128>>>(h, h, g1 + bOff, be1 + bOff, DMODEL, DMODEL, aHi, aLo);

        tgemm_kernel<1,0,1,0><<<gF1, 256, SMEM_GEMM>>>(
            aHi, aLo, wbHi + w1W, wbLo + w1W,
            b1 + b1Off, b1 + b1Off, b1 + b1Off, nullptr, nullptr, fHi, fLo,
            MROWS, DFF, DMODEL);
        tgemm_kernel<0,1,0,0><<<gF2, 256, SMEM_GEMM>>>(
            fHi, fLo, wbHi + w2W, wbLo + w2W,
            b2 + bOff, b2 + bOff, b2 + bOff, h, h, nullptr, nullptr,
            MROWS, DMODEL, DFF);
        ln512_kernel<<<MROWS, 128>>>(h, h, g2 + bOff, be2 + bOff, DMODEL, DMODEL, aHi, aLo);
    }

    ln512_kernel<<<BB, 128>>>(h + (size_t)(LL - 1) * DMODEL, last, g_enc, b_enc,
                              (size_t)LL * DMODEL, DMODEL, nullptr, nullptr);
    head_kernel<<<BB, 256>>>(W_pre, b_pre, W_fc, b_fc, (float*)d_out);
}

// round 8
// speedup vs baseline: 1.4891x; 1.4891x over previous
#include <cuda_runtime.h>
#include <cuda_bf16.h>
#include <math.h>
#include <stdint.h>
#include <stddef.h>

// ---------------- problem dims (fixed) ----------------
#define BB   8
#define LL   2048
#define CIN  32
#define DMODEL 512
#define DFF  2048
#define NH   8
#define HD   64
#define NE   2
#define UU   24
#define MROWS (BB*LL)      // 16384

// converted-weight layout (bf16 element offsets)
// [QKV layer0|layer1][WO l0|l1][W1 l0|l1][W2 l0|l1]
#define QKV_PER_LAYER (1536*512)              // 786432
#define WO_OFF   1572864
#define W1_OFF   2097152
#define W2_OFF   4194304
#define WTOT     6291456
#define WTOT_F4  1572864

// ---------------- scratch ----------------
__device__ float g_xln [MROWS*CIN];
__device__ float g_h   [(size_t)MROWS*DMODEL];
__device__ float g_qkv [(size_t)MROWS*1536];
__device__ float g_M   [BB*NH*LL];
__device__ int   g_samp[LL*UU];
__device__ int   g_idxtop[BB*NH*UU];
__device__ float g_vmean[BB*NH*HD];
__device__ float g_upd [BB*NH*UU*HD];
__device__ float g_last[BB*DMODEL];
__device__ float g_pe  [LL*DMODEL];
__device__ float g_sc  [(size_t)BB*NH*UU*LL];
__device__ float g_S   [BB*NH*UU];
__device__ __nv_bfloat16 g_aHi[(size_t)MROWS*DMODEL];
__device__ __nv_bfloat16 g_aLo[(size_t)MROWS*DMODEL];
__device__ __nv_bfloat16 g_fHi[(size_t)MROWS*DFF];
__device__ __nv_bfloat16 g_fLo[(size_t)MROWS*DFF];
__device__ __nv_bfloat16 g_wbHi[WTOT];
__device__ __nv_bfloat16 g_wbLo[WTOT];

// ================= helpers =================
__device__ __forceinline__ uint32_t packbf(__nv_bfloat16 a, __nv_bfloat16 b) {
    __nv_bfloat162 t = __halves2bfloat162(a, b);
    return *reinterpret_cast<uint32_t*>(&t);
}
__device__ __forceinline__ void mma16816(float* c, const uint32_t* a, const uint32_t* b) {
    asm volatile(
        "mma.sync.aligned.m16n8k16.row.col.f32.bf16.bf16.f32 "
        "{%0,%1,%2,%3}, {%4,%5,%6,%7}, {%8,%9}, {%0,%1,%2,%3};"
        : "+f"(c[0]), "+f"(c[1]), "+f"(c[2]), "+f"(c[3])
        : "r"(a[0]), "r"(a[1]), "r"(a[2]), "r"(a[3]), "r"(b[0]), "r"(b[1]));
}
__device__ __forceinline__ void ldsm4(uint32_t& r0, uint32_t& r1, uint32_t& r2, uint32_t& r3,
                                      uint32_t addr) {
    asm volatile("ldmatrix.sync.aligned.m8n8.x4.shared.b16 {%0,%1,%2,%3}, [%4];"
                 : "=r"(r0), "=r"(r1), "=r"(r2), "=r"(r3) : "r"(addr));
}
#define CP_ASYNC16(dst, src) \
    asm volatile("cp.async.ca.shared.global [%0], [%1], 16;" :: "r"(dst), "l"(src))
#define CP_COMMIT() asm volatile("cp.async.commit_group;" ::: "memory")
#define CP_WAIT1()  asm volatile("cp.async.wait_group 1;" ::: "memory")
#define CP_WAIT0()  asm volatile("cp.async.wait_group 0;" ::: "memory")

__device__ __forceinline__ void stage_tile(uint32_t dstBase, const __nv_bfloat16* src,
                                           int K, int k0, int tid) {
    int row = tid >> 2, c = tid & 3;
    #pragma unroll
    for (int i = 0; i < 2; i++) {
        int r = row + 64 * i;
        uint32_t doff = (uint32_t)(r * 64 + ((c ^ ((r >> 1) & 3)) << 4));
        CP_ASYNC16(dstBase + doff, src + (size_t)r * K + k0 + c * 8);
    }
}

// ================= pipelined bf16x3 tensor GEMM =================
template<int RELU, int RES, int OUT, int SEGB>
__global__ __launch_bounds__(256, 2)
void tgemm_kernel(const __nv_bfloat16* __restrict__ aHi, const __nv_bfloat16* __restrict__ aLo,
                  const __nv_bfloat16* __restrict__ bHi, const __nv_bfloat16* __restrict__ bLo,
                  const float* __restrict__ b0, const float* __restrict__ b1,
                  const float* __restrict__ b2,
                  const float* __restrict__ res, float* __restrict__ C,
                  __nv_bfloat16* __restrict__ outHi, __nv_bfloat16* __restrict__ outLo,
                  int M, int N, int K) {
    extern __shared__ char smem[];
    uint32_t sb = (uint32_t)__cvta_generic_to_shared(smem);

    int tid = threadIdx.x;
    int wid = tid >> 5, lane = tid & 31;
    int warpM = wid >> 2, warpN = wid & 3;
    int bn = blockIdx.x, bm = blockIdx.y;

    const __nv_bfloat16* Ah = aHi + (size_t)(bm * 128) * K;
    const __nv_bfloat16* Al = aLo + (size_t)(bm * 128) * K;
    const __nv_bfloat16* Bh = bHi + (size_t)(bn * 128) * K;
    const __nv_bfloat16* Bl = bLo + (size_t)(bn * 128) * K;

    float acc[4][4][4];
    #pragma unroll
    for (int mt = 0; mt < 4; mt++)
        #pragma unroll
        for (int nt = 0; nt < 4; nt++)
            #pragma unroll
            for (int e = 0; e < 4; e++) acc[mt][nt][e] = 0.f;

    int nchunks = K >> 5;
    {
        stage_tile(sb,         Ah, K, 0, tid);
        stage_tile(sb + 8192,  Al, K, 0, tid);
        stage_tile(sb + 16384, Bh, K, 0, tid);
        stage_tile(sb + 24576, Bl, K, 0, tid);
        CP_COMMIT();
    }
    for (int c = 0; c < nchunks; c++) {
        if (c + 1 < nchunks) {
            uint32_t s1 = sb + ((c + 1) & 1) * 32768;
            int k0 = (c + 1) * 32;
            stage_tile(s1,         Ah, K, k0, tid);
            stage_tile(s1 + 8192,  Al, K, k0, tid);
            stage_tile(s1 + 16384, Bh, K, k0, tid);
            stage_tile(s1 + 24576, Bl, K, k0, tid);
            CP_COMMIT();
            CP_WAIT1();
        } else {
            CP_WAIT0();
        }
        __syncthreads();

        uint32_t st = sb + (c & 1) * 32768;
        #pragma unroll
        for (int pass = 0; pass < 3; pass++) {
            uint32_t aB = st + ((pass == 2) ? 8192 : 0);
            uint32_t bB = st + 16384 + ((pass == 1) ? 8192 : 0);
            #pragma unroll
            for (int ks = 0; ks < 2; ks++) {
                int cidx = ks * 2 + (lane >> 4);
                uint32_t afr[4][4];
                #pragma unroll
                for (int mt = 0; mt < 4; mt++) {
                    int row = warpM * 64 + mt * 16 + (lane & 15);
                    uint32_t addr = aB + row * 64 + ((cidx ^ ((row >> 1) & 3)) << 4);
                    ldsm4(afr[mt][0], afr[mt][1], afr[mt][2], afr[mt][3], addr);
                }
                uint32_t bfr[4][2];
                #pragma unroll
                for (int p = 0; p < 2; p++) {
                    int row = warpN * 32 + p * 16 + (lane & 15);
                    uint32_t addr = bB + row * 64 + ((cidx ^ ((row >> 1) & 3)) << 4);
                    uint32_t r0, r1, r2, r3;
                    ldsm4(r0, r1, r2, r3, addr);
                    bfr[p*2][0] = r0; bfr[p*2+1][0] = r1;
                    bfr[p*2][1] = r2; bfr[p*2+1][1] = r3;
                }
                #pragma unroll
                for (int mt = 0; mt < 4; mt++)
                    #pragma unroll
                    for (int nt = 0; nt < 4; nt++)
                        mma16816(acc[mt][nt], afr[mt], bfr[nt]);
            }
        }
        __syncthreads();
    }

    #pragma unroll
    for (int mt = 0; mt < 4; mt++) {
        int r0 = bm * 128 + warpM * 64 + mt * 16 + (lane >> 2);
        #pragma unroll
        for (int nt = 0; nt < 4; nt++) {
            int cc = bn * 128 + warpN * 32 + nt * 8 + (lane & 3) * 2;
            const float* bp;
            int cb;
            if (SEGB) {
                int seg = cc >> 9;
                bp = (seg == 0) ? b0 : ((seg == 1) ? b1 : b2);
                cb = cc & 511;
            } else { bp = b0; cb = cc; }
            float2 bi = *(const float2*)(bp + cb);
            float2 o0 = make_float2(acc[mt][nt][0] + bi.x, acc[mt][nt][1] + bi.y);
            float2 o1 = make_float2(acc[mt][nt][2] + bi.x, acc[mt][nt][3] + bi.y);
            size_t g0 = (size_t)r0 * N + cc;
            size_t g1 = (size_t)(r0 + 8) * N + cc;
            if (RES) {
                float2 q0 = *(const float2*)(res + g0);
                float2 q1 = *(const float2*)(res + g1);
                o0.x += q0.x; o0.y += q0.y; o1.x += q1.x; o1.y += q1.y;
            }
            if (RELU) {
                o0.x = fmaxf(o0.x, 0.f); o0.y = fmaxf(o0.y, 0.f);
                o1.x = fmaxf(o1.x, 0.f); o1.y = fmaxf(o1.y, 0.f);
            }
            if (OUT == 0) {
                *(float2*)(C + g0) = o0;
                *(float2*)(C + g1) = o1;
            } else {
                __nv_bfloat16 h0 = __float2bfloat16(o0.x), h1 = __float2bfloat16(o0.y);
                __nv_bfloat16 h2 = __float2bfloat16(o1.x), h3 = __float2bfloat16(o1.y);
                *(uint32_t*)(outHi + g0) = packbf(h0, h1);
                *(uint32_t*)(outHi + g1) = packbf(h2, h3);
                *(uint32_t*)(outLo + g0) = packbf(
                    __float2bfloat16(o0.x - __bfloat162float(h0)),
                    __float2bfloat16(o0.y - __bfloat162float(h1)));
                *(uint32_t*)(outLo + g1) = packbf(
                    __float2bfloat16(o1.x - __bfloat162float(h2)),
                    __float2bfloat16(o1.y - __bfloat162float(h3)));
            }
        }
    }
}

// ---------------- all-weight hi/lo conversion (once; QKV|WO|W1|W2) ----------------
__global__ void wconv_kernel(const float4* __restrict__ Wq, const float4* __restrict__ Wk,
                             const float4* __restrict__ Wv, const float4* __restrict__ Wo,
                             const float4* __restrict__ W1, const float4* __restrict__ W2) {
    int j = blockIdx.x * 256 + threadIdx.x;   // float4 index over WTOT_F4
    if (j >= WTOT_F4) return;
    const float4* src;
    if (j < 393216) {
        int layer = j / 196608;
        int r = j - layer * 196608;
        int seg = r >> 16, off = r & 65535;
        const float4* base = (seg == 0) ? Wq : ((seg == 1) ? Wk : Wv);
        src = base + layer * 65536 + off;
    } else if (j < 524288) {
        src = Wo + (j - 393216);
    } else if (j < 1048576) {
        src = W1 + (j - 524288);
    } else {
        src = W2 + (j - 1048576);
    }
    float4 f = *src;
    __nv_bfloat16 h0 = __float2bfloat16(f.x), h1 = __float2bfloat16(f.y);
    __nv_bfloat16 h2 = __float2bfloat16(f.z), h3 = __float2bfloat16(f.w);
    ((uint2*)g_wbHi)[j] = make_uint2(packbf(h0, h1), packbf(h2, h3));
    ((uint2*)g_wbLo)[j] = make_uint2(
        packbf(__float2bfloat16(f.x - __bfloat162float(h0)),
               __float2bfloat16(f.y - __bfloat162float(h1))),
        packbf(__float2bfloat16(f.z - __bfloat162float(h2)),
               __float2bfloat16(f.w - __bfloat162float(h3))));
}

// ---------------- positional-embedding table (once) ----------------
__global__ void pe_kernel() {
    int i2 = blockIdx.x;
    double dv = exp(-(double)(2 * i2) * (9.210340371976184 / 512.0));
    const double TWO_PI = 6.283185307179586;
    const double INV2PI = 0.15915494309189535;
    for (int l = threadIdx.x; l < LL; l += 256) {
        double arg = (double)l * dv;
        double qd = rint(arg * INV2PI);
        double r = fma(-qd, TWO_PI, arg);
        float rf = (float)r;
        g_pe[l * DMODEL + 2 * i2]     = sinf(rf);
        g_pe[l * DMODEL + 2 * i2 + 1] = cosf(rf);
    }
}

// ---------------- threefry2x32 (JAX partitionable) ----------------
__device__ __forceinline__ void tf2x32(uint32_t k0, uint32_t k1,
                                       uint32_t x0, uint32_t x1,
                                       uint32_t& o0, uint32_t& o1) {
    uint32_t ks2 = k0 ^ k1 ^ 0x1BD11BDAu;
    uint32_t v0 = x0 + k0, v1 = x1 + k1;
#define TF_RND(r) { v0 += v1; v1 = (v1 << (r)) | (v1 >> (32 - (r))); v1 ^= v0; }
    TF_RND(13) TF_RND(15) TF_RND(26) TF_RND(6)   v0 += k1;  v1 += ks2 + 1u;
    TF_RND(17) TF_RND(29) TF_RND(16) TF_RND(24)  v0 += ks2; v1 += k0 + 2u;
    TF_RND(13) TF_RND(15) TF_RND(26) TF_RND(6)   v0 += k0;  v1 += k1 + 3u;
    TF_RND(17) TF_RND(29) TF_RND(16) TF_RND(24)  v0 += k1;  v1 += ks2 + 4u;
    TF_RND(13) TF_RND(15) TF_RND(26) TF_RND(6)   v0 += ks2; v1 += k0 + 5u;
#undef TF_RND
    o0 = v0; o1 = v1;
}

__global__ void sample_kernel(int layer) {
    int j = blockIdx.x * blockDim.x + threadIdx.x;
    if (j >= LL * UU) return;
    uint32_t a0, a1;
    tf2x32(0u, 42u, 0u, (uint32_t)layer, a0, a1);
    uint32_t k2a, k2b;
    tf2x32(a0, a1, 0u, 1u, k2a, k2b);
    uint32_t o0, o1;
    tf2x32(k2a, k2b, 0u, (uint32_t)j, o0, o1);
    g_samp[j] = (int)((o0 ^ o1) & 2047u);
}

// ---------------- input layernorm over C_IN=32 ----------------
__global__ void ln32_kernel(const float* __restrict__ x,
                            const float* __restrict__ g, const float* __restrict__ b) {
    int row  = blockIdx.x * 8 + (threadIdx.x >> 5);
    int lane = threadIdx.x & 31;
    float v = x[(size_t)row * CIN + lane];
    float s = v;
    #pragma unroll
    for (int o = 16; o; o >>= 1) s += __shfl_xor_sync(~0u, s, o);
    float m = s * (1.f / 32.f);
    float d = v - m;
    float ss = d * d;
    #pragma unroll
    for (int o = 16; o; o >>= 1) ss += __shfl_xor_sync(~0u, ss, o);
    float r = rsqrtf(ss * (1.f / 32.f) + 1e-5f);
    g_xln[(size_t)row * CIN + lane] = d * r * g[lane] + b[lane];
}

// ---------------- token conv + pe table + time proj ----------------
__global__ void embed_kernel(const float* __restrict__ tfeat,
                             const float* __restrict__ Wtok,
                             const float* __restrict__ Wtime,
                             const float* __restrict__ btime) {
    int bl = blockIdx.x;
    int l = bl & (LL - 1);
    int b = bl >> 11;
    __shared__ float xs[96];
    __shared__ float tf[4];
    int tid = threadIdx.x; // 128
    if (tid < 96) {
        int w = tid / 32, c = tid % 32;
        int lsrc = (l - 1 + w + LL) & (LL - 1);
        xs[tid] = g_xln[((size_t)b * LL + lsrc) * CIN + c];
    }
    if (tid < 4) tf[tid] = tfeat[((size_t)b * LL + l) * 4 + tid];
    __syncthreads();
    for (int m = tid; m < DMODEL; m += 128) {
        float acc = btime[m];
        #pragma unroll 8
        for (int wc = 0; wc < 96; wc++) acc += xs[wc] * Wtok[wc * DMODEL + m];
        #pragma unroll
        for (int t = 0; t < 4; t++) acc += tf[t] * Wtime[m * 4 + t];
        float v = acc + g_pe[l * DMODEL + m];
        size_t idx = ((size_t)b * LL + l) * DMODEL + m;
        g_h[idx] = v;
        __nv_bfloat16 hv = __float2bfloat16(v);
        g_aHi[idx] = hv;
        g_aLo[idx] = __float2bfloat16(v - __bfloat162float(hv));
    }
}

// ---------------- M scores ----------------
__global__ void mscore_kernel() {
    int wid  = (blockIdx.x * blockDim.x + threadIdx.x) >> 5;
    int lane = threadIdx.x & 31;
    if (wid >= BB * NH * LL) return;
    int l = wid & (LL - 1);
    int h = (wid >> 11) & (NH - 1);
    int b = wid >> 14;
    const float* qr = g_qkv + ((size_t)b * LL + l) * 1536 + h * 64;
    float q0 = qr[lane * 2], q1 = qr[lane * 2 + 1];
    float mx = -INFINITY, sm = 0.f;
    #pragma unroll 4
    for (int s = 0; s < UU; s++) {
        int ks = g_samp[l * UU + s];
        const float* kr = g_qkv + ((size_t)b * LL + ks) * 1536 + 512 + h * 64;
        float v = q0 * kr[lane * 2] + q1 * kr[lane * 2 + 1];
        #pragma unroll
        for (int o = 16; o; o >>= 1) v += __shfl_xor_sync(~0u, v, o);
        mx = fmaxf(mx, v);
        sm += v;
    }
    if (lane == 0)
        g_M[((size_t)(b * NH + h)) * LL + l] = mx - sm * (1.0f / (float)LL);
}

// ---------------- top-24 per (b,h), JAX tie semantics ----------------
__global__ void topk_kernel() {
    int bh = blockIdx.x;
    int tid = threadIdx.x;   // 256
    __shared__ float sv[LL];
    __shared__ float rv[256];
    __shared__ int   ri[256];
    for (int i = tid; i < LL; i += 256) sv[i] = g_M[(size_t)bh * LL + i];
    __syncthreads();
    for (int t = 0; t < UU; t++) {
        float bvv = -INFINITY; int bi = LL;
        for (int i = tid; i < LL; i += 256) {
            float v = sv[i];
            if (v > bvv || (v == bvv && i < bi)) { bvv = v; bi = i; }
        }
        rv[tid] = bvv; ri[tid] = bi;
        __syncthreads();
        for (int s = 128; s > 0; s >>= 1) {
            if (tid < s) {
                float v2 = rv[tid + s]; int i2 = ri[tid + s];
                if (v2 > rv[tid] || (v2 == rv[tid] && i2 < ri[tid])) { rv[tid] = v2; ri[tid] = i2; }
            }
            __syncthreads();
        }
        if (tid == 0) { g_idxtop[bh * UU + t] = ri[0]; sv[ri[0]] = -INFINITY; }
        __syncthreads();
    }
}

// ---------------- mean(V) over L ----------------
__global__ void vmean_kernel() {
    int bh = blockIdx.x;
    int h = bh & (NH - 1), b = bh >> 3;
    int tid = threadIdx.x;            // 256
    int d = tid & 63, part = tid >> 6;
    float s = 0.f;
    for (int l = part; l < LL; l += 4)
        s += g_qkv[((size_t)b * LL + l) * 1536 + 1024 + h * 64 + d];
    __shared__ float red[256];
    red[tid] = s; __syncthreads();
    if (tid < 64) {
        float tot = red[tid] + red[tid + 64] + red[tid + 128] + red[tid + 192];
        g_vmean[bh * HD + tid] = tot * (1.0f / (float)LL);
    }
}

// ---------------- scores for selected queries ----------------
__global__ void qkscore_kernel() {   // grid (64, 8), 256 threads
    int bh = blockIdx.x;
    int kt = blockIdx.y;
    int h = bh & 7, b = bh >> 3;
    int tid = threadIdx.x;
    __shared__ float qs[UU * 64];
    __shared__ float sc[UU][256];
    size_t bL = (size_t)b * LL;
    for (int i = tid; i < UU * 64; i += 256) {
        int u = i >> 6, d = i & 63;
        qs[i] = g_qkv[(bL + g_idxtop[bh * UU + u]) * 1536 + h * 64 + d];
    }
    __syncthreads();
    int k = kt * 256 + tid;
    float4 kr[16];
    const float4* kp = (const float4*)(g_qkv + (bL + k) * 1536 + 512 + h * 64);
    #pragma unroll
    for (int i = 0; i < 16; i++) kr[i] = kp[i];
    #pragma unroll 4
    for (int u = 0; u < UU; u++) {
        const float4* qp = (const float4*)(qs + u * 64);
        float s = 0.f;
        #pragma unroll
        for (int i = 0; i < 16; i++) {
            float4 q4 = qp[i];
            s += q4.x * kr[i].x + q4.y * kr[i].y + q4.z * kr[i].z + q4.w * kr[i].w;
        }
        sc[u][tid] = s * 0.125f;
    }
    __syncthreads();
    for (int i = tid; i < UU * 256; i += 256) {
        int u = i >> 8, c = i & 255;
        g_sc[((size_t)bh * UU + u) * LL + kt * 256 + c] = sc[u][c];
    }
}

// ---------------- softmax (exp in-place in g_sc, sum to g_S) ----------------
__global__ void softmax_kernel() {   // grid BB*NH*UU = 1536, 256 threads
    int bid = blockIdx.x;
    int tid = threadIdx.x;
    float* row = g_sc + (size_t)bid * LL;
    __shared__ float red[256];
    float vloc[8];
    float mx = -INFINITY;
    #pragma unroll
    for (int i = 0; i < 8; i++) { vloc[i] = row[tid + 256 * i]; mx = fmaxf(mx, vloc[i]); }
    red[tid] = mx; __syncthreads();
    for (int s = 128; s > 0; s >>= 1) { if (tid < s) red[tid] = fmaxf(red[tid], red[tid+s]); __syncthreads(); }
    mx = red[0]; __syncthreads();
    float sm = 0.f;
    #pragma unroll
    for (int i = 0; i < 8; i++) { float e = expf(vloc[i] - mx); row[tid + 256 * i] = e; sm += e; }
    red[tid] = sm; __syncthreads();
    for (int s = 128; s > 0; s >>= 1) { if (tid < s) red[tid] += red[tid+s]; __syncthreads(); }
    if (tid == 0) g_S[bid] = red[0];
}

// ---------------- batched V pass: one block per (b,h), 24 accumulators ------------
__global__ void attnv_kernel() {     // grid 64, 256 threads
    int bh = blockIdx.x;
    int h = bh & 7, b = bh >> 3;
    int tid = threadIdx.x;
    int d = tid & 63, part = tid >> 6;
    __shared__ float pt[UU][256];
    __shared__ float red[256];
    float acc[UU];
    #pragma unroll
    for (int u = 0; u < UU; u++) acc[u] = 0.f;
    size_t bL = (size_t)b * LL;
    for (int kt = 0; kt < 8; kt++) {
        for (int i = tid; i < UU * 256; i += 256) {
            int u = i >> 8, c = i & 255;
            pt[u][c] = g_sc[((size_t)bh * UU + u) * LL + kt * 256 + c];
        }
        __syncthreads();
        for (int kk = part; kk < 256; kk += 4) {
            float v = g_qkv[(bL + kt * 256 + kk) * 1536 + 1024 + h * 64 + d];
            #pragma unroll
            for (int u = 0; u < UU; u++) acc[u] += pt[u][kk] * v;
        }
        __syncthreads();
    }
    #pragma unroll 1
    for (int u = 0; u < UU; u++) {
        red[tid] = acc[u]; __syncthreads();
        if (tid < 64) {
            float tot = red[tid] + red[tid + 64] + red[tid + 128] + red[tid + 192];
            g_upd[((size_t)bh * UU + u) * HD + tid] = tot / g_S[bh * UU + u];
        }
        __syncthreads();
    }
}

// ---------------- broadcast vmean into bf16 hi/lo attn buffer ----------------
__global__ void fill_kernel() {
    size_t i = (size_t)blockIdx.x * 256 + threadIdx.x;   // pair index
    size_t e = i * 2;
    int d = (int)(e & 63);
    int h = (int)((e >> 6) & 7);
    int b = (int)(e >> 20);
    float v0 = g_vmean[(b * NH + h) * HD + d];
    float v1 = g_vmean[(b * NH + h) * HD + d + 1];
    __nv_bfloat16 h0 = __float2bfloat16(v0), h1 = __float2bfloat16(v1);
    *(uint32_t*)(g_aHi + e) = packbf(h0, h1);
    *(uint32_t*)(g_aLo + e) = packbf(__float2bfloat16(v0 - __bfloat162float(h0)),
                                     __float2bfloat16(v1 - __bfloat162float(h1)));
}

// ---------------- scatter updated rows (bf16 hi/lo) ----------------
__global__ void scatter_kernel() {
    int bid = blockIdx.x;
    int u = bid % UU;
    int bh = bid / UU;
    int h = bh & (NH - 1), b = bh >> 3;
    int qi = g_idxtop[bh * UU + u];
    float v = g_upd[(size_t)bid * HD + threadIdx.x];
    size_t idx = (((size_t)b * LL + qi) * NH + h) * HD + threadIdx.x;
    __nv_bfloat16 hv = __float2bfloat16(v);
    g_aHi[idx] = hv;
    g_aLo[idx] = __float2bfloat16(v - __bfloat162float(hv));
}

// ---------------- layernorm over 512 (optionally emits hi/lo) ----------------
__global__ void ln512_kernel(const float* __restrict__ in, float* __restrict__ out,
                             const float* __restrict__ g, const float* __restrict__ b,
                             size_t strideIn, size_t strideOut,
                             __nv_bfloat16* __restrict__ hiOut,
                             __nv_bfloat16* __restrict__ loOut) {
    int row = blockIdx.x;
    int tid = threadIdx.x;  // 128
    const float* x = in + (size_t)row * strideIn;
    float4 v = *(const float4*)(x + tid * 4);
    float s  = v.x + v.y + v.z + v.w;
    float ss = v.x*v.x + v.y*v.y + v.z*v.z + v.w*v.w;
    __shared__ float rs[4], rss[4];
    #pragma unroll
    for (int o = 16; o; o >>= 1) {
        s  += __shfl_xor_sync(~0u, s, o);
        ss += __shfl_xor_sync(~0u, ss, o);
    }
    int w = tid >> 5, lane = tid & 31;
    if (lane == 0) { rs[w] = s; rss[w] = ss; }
    __syncthreads();
    s  = rs[0] + rs[1] + rs[2] + rs[3];
    ss = rss[0] + rss[1] + rss[2] + rss[3];
    float m = s * (1.f / 512.f);
    float var = ss * (1.f / 512.f) - m * m;
    float r = rsqrtf(var + 1e-5f);
    float4 gg = *(const float4*)(g + tid * 4);
    float4 bb = *(const float4*)(b + tid * 4);
    float4 o4;
    o4.x = (v.x - m) * r * gg.x + bb.x;
    o4.y = (v.y - m) * r * gg.y + bb.y;
    o4.z = (v.z - m) * r * gg.z + bb.z;
    o4.w = (v.w - m) * r * gg.w + bb.w;
    *(float4*)(out + (size_t)row * strideOut + tid * 4) = o4;
    if (hiOut) {
        size_t e = (size_t)row * DMODEL + tid * 4;
        __nv_bfloat16 h0 = __float2bfloat16(o4.x), h1 = __float2bfloat16(o4.y);
        __nv_bfloat16 h2 = __float2bfloat16(o4.z), h3 = __float2bfloat16(o4.w);
        *(uint2*)(hiOut + e) = make_uint2(packbf(h0, h1), packbf(h2, h3));
        *(uint2*)(loOut + e) = make_uint2(
            packbf(__float2bfloat16(o4.x - __bfloat162float(h0)),
                   __float2bfloat16(o4.y - __bfloat162float(h1))),
            packbf(__float2bfloat16(o4.z - __bfloat162float(h2)),
                   __float2bfloat16(o4.w - __bfloat162float(h3))));
    }
}

// ---------------- final head ----------------
__global__ void head_kernel(const float* __restrict__ Wpre, const float* __restrict__ bpre,
                            const float* __restrict__ Wfc,  const float* __restrict__ bfc,
                            float* __restrict__ out) {
    int b = blockIdx.x;
    int tid = threadIdx.x;  // 256
    __shared__ float red[256];
    const float* x = g_last + (size_t)b * DMODEL;
    float acc = bpre[tid];
    const float* w = Wpre + (size_t)tid * DMODEL;
    #pragma unroll 8
    for (int k = 0; k < DMODEL; k++) acc += x[k] * w[k];
    float pre = fmaxf(acc, 0.f);
    red[tid] = pre * Wfc[tid];
    __syncthreads();
    for (int s = 128; s > 0; s >>= 1) { if (tid < s) red[tid] += red[tid + s]; __syncthreads(); }
    if (tid == 0) out[b] = red[0] + bfc[0];
}

// ---------------- host orchestration ----------------
#define SMEM_GEMM 65536

extern "C" void kernel_launch(void* const* d_in, const int* in_sizes, int n_in,
                              void* d_out, int out_size) {
    const float* x      = (const float*)d_in[0];
    const float* tfeat  = (const float*)d_in[1];
    const float* g_in   = (const float*)d_in[2];
    const float* b_in   = (const float*)d_in[3];
    const float* W_tok  = (const float*)d_in[4];
    const float* W_time = (const float*)d_in[5];
    const float* b_time = (const float*)d_in[6];
    const float* Wq     = (const float*)d_in[7];
    const float* bq     = (const float*)d_in[8];
    const float* Wk     = (const float*)d_in[9];
    const float* bk     = (const float*)d_in[10];
    const float* Wv     = (const float*)d_in[11];
    const float* bv     = (const float*)d_in[12];
    const float* Wo     = (const float*)d_in[13];
    const float* bo     = (const float*)d_in[14];
    const float* W1     = (const float*)d_in[15];
    const float* b1     = (const float*)d_in[16];
    const float* W2     = (const float*)d_in[17];
    const float* b2     = (const float*)d_in[18];
    const float* g1     = (const float*)d_in[19];
    const float* be1    = (const float*)d_in[20];
    const float* g2     = (const float*)d_in[21];
    const float* be2    = (const float*)d_in[22];
    const float* g_enc  = (const float*)d_in[23];
    const float* b_enc  = (const float*)d_in[24];
    const float* W_pre  = (const float*)d_in[25];
    const float* b_pre  = (const float*)d_in[26];
    const float* W_fc   = (const float*)d_in[27];
    const float* b_fc   = (const float*)d_in[28];

    float *h, *qkv, *last;
    __nv_bfloat16 *aHi, *aLo, *fHi, *fLo, *wbHi, *wbLo;
    cudaGetSymbolAddress((void**)&h,    g_h);
    cudaGetSymbolAddress((void**)&qkv,  g_qkv);
    cudaGetSymbolAddress((void**)&last, g_last);
    cudaGetSymbolAddress((void**)&aHi,  g_aHi);
    cudaGetSymbolAddress((void**)&aLo,  g_aLo);
    cudaGetSymbolAddress((void**)&fHi,  g_fHi);
    cudaGetSymbolAddress((void**)&fLo,  g_fLo);
    cudaGetSymbolAddress((void**)&wbHi, g_wbHi);
    cudaGetSymbolAddress((void**)&wbLo, g_wbLo);

    cudaFuncSetAttribute(tgemm_kernel<0,0,0,1>, cudaFuncAttributeMaxDynamicSharedMemorySize, SMEM_GEMM);
    cudaFuncSetAttribute(tgemm_kernel<1,0,1,0>, cudaFuncAttributeMaxDynamicSharedMemorySize, SMEM_GEMM);
    cudaFuncSetAttribute(tgemm_kernel<0,1,0,0>, cudaFuncAttributeMaxDynamicSharedMemorySize, SMEM_GEMM);

    pe_kernel<<<256, 256>>>();
    ln32_kernel<<<MROWS / 8, 256>>>(x, g_in, b_in);
    embed_kernel<<<MROWS, 128>>>(tfeat, W_tok, W_time, b_time);
    wconv_kernel<<<WTOT_F4 / 256, 256>>>((const float4*)Wq, (const float4*)Wk,
                                         (const float4*)Wv, (const float4*)Wo,
                                         (const float4*)W1, (const float4*)W2);

    dim3 gQKV(1536 / 128, MROWS / 128);   // (12,128)
    dim3 gO(DMODEL / 128, MROWS / 128);   // (4,128)
    dim3 gF1(DFF / 128,  MROWS / 128);    // (16,128)
    dim3 gF2(DMODEL / 128, MROWS / 128);  // (4,128)

    for (int i = 0; i < NE; i++) {
        size_t bOff  = (size_t)i * DMODEL;
        size_t b1Off = (size_t)i * DFF;
        size_t qkvW  = (size_t)i * QKV_PER_LAYER;
        size_t woW   = WO_OFF + (size_t)i * DMODEL * DMODEL;
        size_t w1W   = W1_OFF + (size_t)i * DFF * DMODEL;
        size_t w2W   = W2_OFF + (size_t)i * DFF * DMODEL;

        sample_kernel<<<(LL * UU + 255) / 256, 256>>>(i);

        tgemm_kernel<0,0,0,1><<<gQKV, 256, SMEM_GEMM>>>(
            aHi, aLo, wbHi + qkvW, wbLo + qkvW,
            bq + bOff, bk + bOff, bv + bOff, nullptr, qkv, nullptr, nullptr,
            MROWS, 1536, DMODEL);

        mscore_kernel<<<(BB * NH * LL * 32) / 256, 256>>>();
        topk_kernel<<<BB * NH, 256>>>();
        vmean_kernel<<<BB * NH, 256>>>();
        qkscore_kernel<<<dim3(BB * NH, 8), 256>>>();
        softmax_kernel<<<BB * NH * UU, 256>>>();
        attnv_kernel<<<BB * NH, 256>>>();
        fill_kernel<<<(MROWS * DMODEL / 2) / 256, 256>>>();
        scatter_kernel<<<BB * NH * UU, HD>>>();

        tgemm_kernel<0,1,0,0><<<gO, 256, SMEM_GEMM>>>(
            aHi, aLo, wbHi + woW, wbLo + woW,
            bo + bOff, nullptr, nullptr, h, h, nullptr, nullptr,
            MROWS, DMODEL, DMODEL);
        ln512_kernel<<<MROWS, 128>>>(h, h, g1 + bOff, be1 + bOff, DMODEL, DMODEL, aHi, aLo);

        tgemm_kernel<1,0,1,0><<<gF1, 256, SMEM_GEMM>>>(
            aHi, aLo, wbHi + w1W, wbLo + w1W,
            b1 + b1Off, nullptr, nullptr, nullptr, nullptr, fHi, fLo,
            MROWS, DFF, DMODEL);
        tgemm_kernel<0,1,0,0><<<gF2, 256, SMEM_GEMM>>>(
            fHi, fLo, wbHi + w2W, wbLo + w2W,
            b2 + bOff, nullptr, nullptr, h, h, nullptr, nullptr,
            MROWS, DMODEL, DFF);
        ln512_kernel<<<MROWS, 128>>>(h, h, g2 + bOff, be2 + bOff, DMODEL, DMODEL, aHi, aLo);
    }

    ln512_kernel<<<BB, 128>>>(h + (size_t)(LL - 1) * DMODEL, last, g_enc, b_enc,
                              (size_t)LL * DMODEL, DMODEL, nullptr, nullptr);
    head_kernel<<<BB, 256>>>(W_pre, b_pre, W_fc, b_fc, (float*)d_out);
}

// round 9
// speedup vs baseline: 1.5215x; 1.0217x over previous
#include <cuda_runtime.h>
#include <cuda_bf16.h>
#include <math.h>
#include <stdint.h>
#include <stddef.h>

// ---------------- problem dims (fixed) ----------------
#define BB   8
#define LL   2048
#define CIN  32
#define DMODEL 512
#define DFF  2048
#define NH   8
#define HD   64
#define NE   2
#define UU   24
#define MROWS (BB*LL)      // 16384

// converted-weight layout (bf16 element offsets)
#define QKV_PER_LAYER (1536*512)
#define WO_OFF   1572864
#define W1_OFF   2097152
#define W2_OFF   4194304
#define WTOT     6291456
#define WTOT_F4  1572864

// ---------------- scratch ----------------
__device__ float g_xln [MROWS*CIN];
__device__ float g_h   [(size_t)MROWS*DMODEL];
__device__ float g_qkv [(size_t)MROWS*1536];
__device__ float g_M   [BB*NH*LL];
__device__ int   g_samp[LL*UU];
__device__ int   g_idxtop[BB*NH*UU];
__device__ float g_vmean[BB*NH*HD];
__device__ float g_upd [BB*NH*UU*HD];
__device__ float g_last[BB*DMODEL];
__device__ float g_pe  [LL*DMODEL];
__device__ float g_sc  [(size_t)BB*NH*UU*LL];
__device__ float g_S   [BB*NH*UU];
__device__ __nv_bfloat16 g_aHi[(size_t)MROWS*DMODEL];
__device__ __nv_bfloat16 g_aLo[(size_t)MROWS*DMODEL];
__device__ __nv_bfloat16 g_fHi[(size_t)MROWS*DFF];
__device__ __nv_bfloat16 g_fLo[(size_t)MROWS*DFF];
__device__ __nv_bfloat16 g_wbHi[WTOT];
__device__ __nv_bfloat16 g_wbLo[WTOT];

// ================= helpers =================
__device__ __forceinline__ uint32_t packbf(__nv_bfloat16 a, __nv_bfloat16 b) {
    __nv_bfloat162 t = __halves2bfloat162(a, b);
    return *reinterpret_cast<uint32_t*>(&t);
}
__device__ __forceinline__ void mma16816(float* c, const uint32_t* a, const uint32_t* b) {
    asm volatile(
        "mma.sync.aligned.m16n8k16.row.col.f32.bf16.bf16.f32 "
        "{%0,%1,%2,%3}, {%4,%5,%6,%7}, {%8,%9}, {%0,%1,%2,%3};"
        : "+f"(c[0]), "+f"(c[1]), "+f"(c[2]), "+f"(c[3])
        : "r"(a[0]), "r"(a[1]), "r"(a[2]), "r"(a[3]), "r"(b[0]), "r"(b[1]));
}
__device__ __forceinline__ void ldsm4(uint32_t& r0, uint32_t& r1, uint32_t& r2, uint32_t& r3,
                                      uint32_t addr) {
    asm volatile("ldmatrix.sync.aligned.m8n8.x4.shared.b16 {%0,%1,%2,%3}, [%4];"
                 : "=r"(r0), "=r"(r1), "=r"(r2), "=r"(r3) : "r"(addr));
}
#define CP_ASYNC16(dst, src) \
    asm volatile("cp.async.ca.shared.global [%0], [%1], 16;" :: "r"(dst), "l"(src))
#define CP_COMMIT() asm volatile("cp.async.commit_group;" ::: "memory")
#define CP_WAIT1()  asm volatile("cp.async.wait_group 1;" ::: "memory")
#define CP_WAIT0()  asm volatile("cp.async.wait_group 0;" ::: "memory")

__device__ __forceinline__ void stage_tile(uint32_t dstBase, const __nv_bfloat16* src,
                                           int K, int k0, int tid) {
    int row = tid >> 2, c = tid & 3;
    #pragma unroll
    for (int i = 0; i < 2; i++) {
        int r = row + 64 * i;
        uint32_t doff = (uint32_t)(r * 64 + ((c ^ ((r >> 1) & 3)) << 4));
        CP_ASYNC16(dstBase + doff, src + (size_t)r * K + k0 + c * 8);
    }
}

// ================= 3-stage pipelined bf16x3 tensor GEMM =================
// Stage = 32KB (Ah|Al|Bh|Bl of a BK=32 chunk). 3 stages/CTA, 2 CTAs/SM.
template<int RELU, int RES, int OUT, int SEGB>
__global__ __launch_bounds__(256, 2)
void tgemm_kernel(const __nv_bfloat16* __restrict__ aHi, const __nv_bfloat16* __restrict__ aLo,
                  const __nv_bfloat16* __restrict__ bHi, const __nv_bfloat16* __restrict__ bLo,
                  const float* __restrict__ b0, const float* __restrict__ b1,
                  const float* __restrict__ b2,
                  const float* __restrict__ res, float* __restrict__ C,
                  __nv_bfloat16* __restrict__ outHi, __nv_bfloat16* __restrict__ outLo,
                  int M, int N, int K) {
    extern __shared__ char smem[];
    uint32_t sb = (uint32_t)__cvta_generic_to_shared(smem);

    int tid = threadIdx.x;
    int wid = tid >> 5, lane = tid & 31;
    int warpM = wid >> 2, warpN = wid & 3;
    int bn = blockIdx.x, bm = blockIdx.y;

    const __nv_bfloat16* Ah = aHi + (size_t)(bm * 128) * K;
    const __nv_bfloat16* Al = aLo + (size_t)(bm * 128) * K;
    const __nv_bfloat16* Bh = bHi + (size_t)(bn * 128) * K;
    const __nv_bfloat16* Bl = bLo + (size_t)(bn * 128) * K;

    float acc[4][4][4];
    #pragma unroll
    for (int mt = 0; mt < 4; mt++)
        #pragma unroll
        for (int nt = 0; nt < 4; nt++)
            #pragma unroll
            for (int e = 0; e < 4; e++) acc[mt][nt][e] = 0.f;

    int nchunks = K >> 5;
    // prologue: stages 0, 1
    #pragma unroll
    for (int s = 0; s < 2; s++) {
        uint32_t sd = sb + s * 32768;
        stage_tile(sd,         Ah, K, s * 32, tid);
        stage_tile(sd + 8192,  Al, K, s * 32, tid);
        stage_tile(sd + 16384, Bh, K, s * 32, tid);
        stage_tile(sd + 24576, Bl, K, s * 32, tid);
        CP_COMMIT();
    }

    int slot = 0;       // slot of chunk c (c % 3)
    int nslot = 2;      // slot for chunk c+2
    for (int c = 0; c < nchunks; c++) {
        if (c + 1 < nchunks) CP_WAIT1(); else CP_WAIT0();
        __syncthreads();   // stage c visible to all; compute(c-1) finished by all
        if (c + 2 < nchunks) {
            uint32_t sd = sb + nslot * 32768;
            int k0 = (c + 2) * 32;
            stage_tile(sd,         Ah, K, k0, tid);
            stage_tile(sd + 8192,  Al, K, k0, tid);
            stage_tile(sd + 16384, Bh, K, k0, tid);
            stage_tile(sd + 24576, Bl, K, k0, tid);
            CP_COMMIT();
        }

        uint32_t st = sb + slot * 32768;
        #pragma unroll
        for (int ks = 0; ks < 2; ks++) {
            int cidx = ks * 2 + (lane >> 4);
            int arow = warpM * 64 + (lane & 15);
            int brow = warpN * 32 + (lane & 15);
            uint32_t a4[4][4];
            uint32_t bh4[4][2], bl4[4][2];
            // A-hi fragments
            #pragma unroll
            for (int mt = 0; mt < 4; mt++) {
                int row = arow + mt * 16;
                ldsm4(a4[mt][0], a4[mt][1], a4[mt][2], a4[mt][3],
                      st + row * 64 + ((cidx ^ ((row >> 1) & 3)) << 4));
            }
            // B-hi and B-lo fragments
            #pragma unroll
            for (int p = 0; p < 2; p++) {
                int row = brow + p * 16;
                uint32_t off = (uint32_t)(row * 64 + ((cidx ^ ((row >> 1) & 3)) << 4));
                uint32_t r0, r1, r2, r3;
                ldsm4(r0, r1, r2, r3, st + 16384 + off);
                bh4[p*2][0] = r0; bh4[p*2+1][0] = r1;
                bh4[p*2][1] = r2; bh4[p*2+1][1] = r3;
                ldsm4(r0, r1, r2, r3, st + 24576 + off);
                bl4[p*2][0] = r0; bl4[p*2+1][0] = r1;
                bl4[p*2][1] = r2; bl4[p*2+1][1] = r3;
            }
            // Ah*Bh + Ah*Bl
            #pragma unroll
            for (int mt = 0; mt < 4; mt++)
                #pragma unroll
                for (int nt = 0; nt < 4; nt++)
                    mma16816(acc[mt][nt], a4[mt], bh4[nt]);
            #pragma unroll
            for (int mt = 0; mt < 4; mt++)
                #pragma unroll
                for (int nt = 0; nt < 4; nt++)
                    mma16816(acc[mt][nt], a4[mt], bl4[nt]);
            // overwrite A with lo, Al*Bh
            #pragma unroll
            for (int mt = 0; mt < 4; mt++) {
                int row = arow + mt * 16;
                ldsm4(a4[mt][0], a4[mt][1], a4[mt][2], a4[mt][3],
                      st + 8192 + row * 64 + ((cidx ^ ((row >> 1) & 3)) << 4));
            }
            #pragma unroll
            for (int mt = 0; mt < 4; mt++)
                #pragma unroll
                for (int nt = 0; nt < 4; nt++)
                    mma16816(acc[mt][nt], a4[mt], bh4[nt]);
        }
        slot = (slot == 2) ? 0 : slot + 1;
        nslot = (nslot == 2) ? 0 : nslot + 1;
    }

    #pragma unroll
    for (int mt = 0; mt < 4; mt++) {
        int r0 = bm * 128 + warpM * 64 + mt * 16 + (lane >> 2);
        #pragma unroll
        for (int nt = 0; nt < 4; nt++) {
            int cc = bn * 128 + warpN * 32 + nt * 8 + (lane & 3) * 2;
            const float* bp;
            int cb;
            if (SEGB) {
                int seg = cc >> 9;
                bp = (seg == 0) ? b0 : ((seg == 1) ? b1 : b2);
                cb = cc & 511;
            } else { bp = b0; cb = cc; }
            float2 bi = *(const float2*)(bp + cb);
            float2 o0 = make_float2(acc[mt][nt][0] + bi.x, acc[mt][nt][1] + bi.y);
            float2 o1 = make_float2(acc[mt][nt][2] + bi.x, acc[mt][nt][3] + bi.y);
            size_t g0 = (size_t)r0 * N + cc;
            size_t g1 = (size_t)(r0 + 8) * N + cc;
            if (RES) {
                float2 q0 = *(const float2*)(res + g0);
                float2 q1 = *(const float2*)(res + g1);
                o0.x += q0.x; o0.y += q0.y; o1.x += q1.x; o1.y += q1.y;
            }
            if (RELU) {
                o0.x = fmaxf(o0.x, 0.f); o0.y = fmaxf(o0.y, 0.f);
                o1.x = fmaxf(o1.x, 0.f); o1.y = fmaxf(o1.y, 0.f);
            }
            if (OUT == 0) {
                *(float2*)(C + g0) = o0;
                *(float2*)(C + g1) = o1;
            } else {
                __nv_bfloat16 h0 = __float2bfloat16(o0.x), h1 = __float2bfloat16(o0.y);
                __nv_bfloat16 h2 = __float2bfloat16(o1.x), h3 = __float2bfloat16(o1.y);
                *(uint32_t*)(outHi + g0) = packbf(h0, h1);
                *(uint32_t*)(outHi + g1) = packbf(h2, h3);
                *(uint32_t*)(outLo + g0) = packbf(
                    __float2bfloat16(o0.x - __bfloat162float(h0)),
                    __float2bfloat16(o0.y - __bfloat162float(h1)));
                *(uint32_t*)(outLo + g1) = packbf(
                    __float2bfloat16(o1.x - __bfloat162float(h2)),
                    __float2bfloat16(o1.y - __bfloat162float(h3)));
            }
        }
    }
}

// ---------------- all-weight hi/lo conversion (once; QKV|WO|W1|W2) ----------------
__global__ void wconv_kernel(const float4* __restrict__ Wq, const float4* __restrict__ Wk,
                             const float4* __restrict__ Wv, const float4* __restrict__ Wo,
                             const float4* __restrict__ W1, const float4* __restrict__ W2) {
    int j = blockIdx.x * 256 + threadIdx.x;
    if (j >= WTOT_F4) return;
    const float4* src;
    if (j < 393216) {
        int layer = j / 196608;
        int r = j - layer * 196608;
        int seg = r >> 16, off = r & 65535;
        const float4* base = (seg == 0) ? Wq : ((seg == 1) ? Wk : Wv);
        src = base + layer * 65536 + off;
    } else if (j < 524288) {
        src = Wo + (j - 393216);
    } else if (j < 1048576) {
        src = W1 + (j - 524288);
    } else {
        src = W2 + (j - 1048576);
    }
    float4 f = *src;
    __nv_bfloat16 h0 = __float2bfloat16(f.x), h1 = __float2bfloat16(f.y);
    __nv_bfloat16 h2 = __float2bfloat16(f.z), h3 = __float2bfloat16(f.w);
    ((uint2*)g_wbHi)[j] = make_uint2(packbf(h0, h1), packbf(h2, h3));
    ((uint2*)g_wbLo)[j] = make_uint2(
        packbf(__float2bfloat16(f.x - __bfloat162float(h0)),
               __float2bfloat16(f.y - __bfloat162float(h1))),
        packbf(__float2bfloat16(f.z - __bfloat162float(h2)),
               __float2bfloat16(f.w - __bfloat162float(h3))));
}

// ---------------- positional-embedding table (once) ----------------
__global__ void pe_kernel() {
    int i2 = blockIdx.x;
    double dv = exp(-(double)(2 * i2) * (9.210340371976184 / 512.0));
    const double TWO_PI = 6.283185307179586;
    const double INV2PI = 0.15915494309189535;
    for (int l = threadIdx.x; l < LL; l += 256) {
        double arg = (double)l * dv;
        double qd = rint(arg * INV2PI);
        double r = fma(-qd, TWO_PI, arg);
        float rf = (float)r;
        g_pe[l * DMODEL + 2 * i2]     = sinf(rf);
        g_pe[l * DMODEL + 2 * i2 + 1] = cosf(rf);
    }
}

// ---------------- threefry2x32 (JAX partitionable) ----------------
__device__ __forceinline__ void tf2x32(uint32_t k0, uint32_t k1,
                                       uint32_t x0, uint32_t x1,
                                       uint32_t& o0, uint32_t& o1) {
    uint32_t ks2 = k0 ^ k1 ^ 0x1BD11BDAu;
    uint32_t v0 = x0 + k0, v1 = x1 + k1;
#define TF_RND(r) { v0 += v1; v1 = (v1 << (r)) | (v1 >> (32 - (r))); v1 ^= v0; }
    TF_RND(13) TF_RND(15) TF_RND(26) TF_RND(6)   v0 += k1;  v1 += ks2 + 1u;
    TF_RND(17) TF_RND(29) TF_RND(16) TF_RND(24)  v0 += ks2; v1 += k0 + 2u;
    TF_RND(13) TF_RND(15) TF_RND(26) TF_RND(6)   v0 += k0;  v1 += k1 + 3u;
    TF_RND(17) TF_RND(29) TF_RND(16) TF_RND(24)  v0 += k1;  v1 += ks2 + 4u;
    TF_RND(13) TF_RND(15) TF_RND(26) TF_RND(6)   v0 += ks2; v1 += k0 + 5u;
#undef TF_RND
    o0 = v0; o1 = v1;
}

__global__ void sample_kernel(int layer) {
    int j = blockIdx.x * blockDim.x + threadIdx.x;
    if (j >= LL * UU) return;
    uint32_t a0, a1;
    tf2x32(0u, 42u, 0u, (uint32_t)layer, a0, a1);
    uint32_t k2a, k2b;
    tf2x32(a0, a1, 0u, 1u, k2a, k2b);
    uint32_t o0, o1;
    tf2x32(k2a, k2b, 0u, (uint32_t)j, o0, o1);
    g_samp[j] = (int)((o0 ^ o1) & 2047u);
}

// ---------------- input layernorm over C_IN=32 ----------------
__global__ void ln32_kernel(const float* __restrict__ x,
                            const float* __restrict__ g, const float* __restrict__ b) {
    int row  = blockIdx.x * 8 + (threadIdx.x >> 5);
    int lane = threadIdx.x & 31;
    float v = x[(size_t)row * CIN + lane];
    float s = v;
    #pragma unroll
    for (int o = 16; o; o >>= 1) s += __shfl_xor_sync(~0u, s, o);
    float m = s * (1.f / 32.f);
    float d = v - m;
    float ss = d * d;
    #pragma unroll
    for (int o = 16; o; o >>= 1) ss += __shfl_xor_sync(~0u, ss, o);
    float r = rsqrtf(ss * (1.f / 32.f) + 1e-5f);
    g_xln[(size_t)row * CIN + lane] = d * r * g[lane] + b[lane];
}

// ---------------- token conv + pe table + time proj ----------------
__global__ void embed_kernel(const float* __restrict__ tfeat,
                             const float* __restrict__ Wtok,
                             const float* __restrict__ Wtime,
                             const float* __restrict__ btime) {
    int bl = blockIdx.x;
    int l = bl & (LL - 1);
    int b = bl >> 11;
    __shared__ float xs[96];
    __shared__ float tf[4];
    int tid = threadIdx.x; // 128
    if (tid < 96) {
        int w = tid / 32, c = tid % 32;
        int lsrc = (l - 1 + w + LL) & (LL - 1);
        xs[tid] = g_xln[((size_t)b * LL + lsrc) * CIN + c];
    }
    if (tid < 4) tf[tid] = tfeat[((size_t)b * LL + l) * 4 + tid];
    __syncthreads();
    for (int m = tid; m < DMODEL; m += 128) {
        float acc = btime[m];
        #pragma unroll 8
        for (int wc = 0; wc < 96; wc++) acc += xs[wc] * Wtok[wc * DMODEL + m];
        #pragma unroll
        for (int t = 0; t < 4; t++) acc += tf[t] * Wtime[m * 4 + t];
        float v = acc + g_pe[l * DMODEL + m];
        size_t idx = ((size_t)b * LL + l) * DMODEL + m;
        g_h[idx] = v;
        __nv_bfloat16 hv = __float2bfloat16(v);
        g_aHi[idx] = hv;
        g_aLo[idx] = __float2bfloat16(v - __bfloat162float(hv));
    }
}

// ---------------- M scores ----------------
__global__ void mscore_kernel() {
    int wid  = (blockIdx.x * blockDim.x + threadIdx.x) >> 5;
    int lane = threadIdx.x & 31;
    if (wid >= BB * NH * LL) return;
    int l = wid & (LL - 1);
    int h = (wid >> 11) & (NH - 1);
    int b = wid >> 14;
    const float* qr = g_qkv + ((size_t)b * LL + l) * 1536 + h * 64;
    float q0 = qr[lane * 2], q1 = qr[lane * 2 + 1];
    float mx = -INFINITY, sm = 0.f;
    #pragma unroll 4
    for (int s = 0; s < UU; s++) {
        int ks = g_samp[l * UU + s];
        const float* kr = g_qkv + ((size_t)b * LL + ks) * 1536 + 512 + h * 64;
        float v = q0 * kr[lane * 2] + q1 * kr[lane * 2 + 1];
        #pragma unroll
        for (int o = 16; o; o >>= 1) v += __shfl_xor_sync(~0u, v, o);
        mx = fmaxf(mx, v);
        sm += v;
    }
    if (lane == 0)
        g_M[((size_t)(b * NH + h)) * LL + l] = mx - sm * (1.0f / (float)LL);
}

// ---------------- top-24 per (b,h), JAX tie semantics ----------------
__global__ void topk_kernel() {
    int bh = blockIdx.x;
    int tid = threadIdx.x;   // 256
    __shared__ float sv[LL];
    __shared__ float rv[256];
    __shared__ int   ri[256];
    for (int i = tid; i < LL; i += 256) sv[i] = g_M[(size_t)bh * LL + i];
    __syncthreads();
    for (int t = 0; t < UU; t++) {
        float bvv = -INFINITY; int bi = LL;
        for (int i = tid; i < LL; i += 256) {
            float v = sv[i];
            if (v > bvv || (v == bvv && i < bi)) { bvv = v; bi = i; }
        }
        rv[tid] = bvv; ri[tid] = bi;
        __syncthreads();
        for (int s = 128; s > 0; s >>= 1) {
            if (tid < s) {
                float v2 = rv[tid + s]; int i2 = ri[tid + s];
                if (v2 > rv[tid] || (v2 == rv[tid] && i2 < ri[tid])) { rv[tid] = v2; ri[tid] = i2; }
            }
            __syncthreads();
        }
        if (tid == 0) { g_idxtop[bh * UU + t] = ri[0]; sv[ri[0]] = -INFINITY; }
        __syncthreads();
    }
}

// ---------------- mean(V) over L ----------------
__global__ void vmean_kernel() {
    int bh = blockIdx.x;
    int h = bh & (NH - 1), b = bh >> 3;
    int tid = threadIdx.x;            // 256
    int d = tid & 63, part = tid >> 6;
    float s = 0.f;
    for (int l = part; l < LL; l += 4)
        s += g_qkv[((size_t)b * LL + l) * 1536 + 1024 + h * 64 + d];
    __shared__ float red[256];
    red[tid] = s; __syncthreads();
    if (tid < 64) {
        float tot = red[tid] + red[tid + 64] + red[tid + 128] + red[tid + 192];
        g_vmean[bh * HD + tid] = tot * (1.0f / (float)LL);
    }
}

// ---------------- scores for selected queries ----------------
__global__ void qkscore_kernel() {   // grid (64, 8), 256 threads
    int bh = blockIdx.x;
    int kt = blockIdx.y;
    int h = bh & 7, b = bh >> 3;
    int tid = threadIdx.x;
    __shared__ float qs[UU * 64];
    __shared__ float sc[UU][256];
    size_t bL = (size_t)b * LL;
    for (int i = tid; i < UU * 64; i += 256) {
        int u = i >> 6, d = i & 63;
        qs[i] = g_qkv[(bL + g_idxtop[bh * UU + u]) * 1536 + h * 64 + d];
    }
    __syncthreads();
    int k = kt * 256 + tid;
    float4 kr[16];
    const float4* kp = (const float4*)(g_qkv + (bL + k) * 1536 + 512 + h * 64);
    #pragma unroll
    for (int i = 0; i < 16; i++) kr[i] = kp[i];
    #pragma unroll 4
    for (int u = 0; u < UU; u++) {
        const float4* qp = (const float4*)(qs + u * 64);
        float s = 0.f;
        #pragma unroll
        for (int i = 0; i < 16; i++) {
            float4 q4 = qp[i];
            s += q4.x * kr[i].x + q4.y * kr[i].y + q4.z * kr[i].z + q4.w * kr[i].w;
        }
        sc[u][tid] = s * 0.125f;
    }
    __syncthreads();
    for (int i = tid; i < UU * 256; i += 256) {
        int u = i >> 8, c = i & 255;
        g_sc[((size_t)bh * UU + u) * LL + kt * 256 + c] = sc[u][c];
    }
}

// ---------------- softmax (exp in-place in g_sc, sum to g_S) ----------------
__global__ void softmax_kernel() {   // grid 1536, 256 threads
    int bid = blockIdx.x;
    int tid = threadIdx.x;
    float* row = g_sc + (size_t)bid * LL;
    __shared__ float red[256];
    float vloc[8];
    float mx = -INFINITY;
    #pragma unroll
    for (int i = 0; i < 8; i++) { vloc[i] = row[tid + 256 * i]; mx = fmaxf(mx, vloc[i]); }
    red[tid] = mx; __syncthreads();
    for (int s = 128; s > 0; s >>= 1) { if (tid < s) red[tid] = fmaxf(red[tid], red[tid+s]); __syncthreads(); }
    mx = red[0]; __syncthreads();
    float sm = 0.f;
    #pragma unroll
    for (int i = 0; i < 8; i++) { float e = expf(vloc[i] - mx); row[tid + 256 * i] = e; sm += e; }
    red[tid] = sm; __syncthreads();
    for (int s = 128; s > 0; s >>= 1) { if (tid < s) red[tid] += red[tid+s]; __syncthreads(); }
    if (tid == 0) g_S[bid] = red[0];
}

// ---------------- batched V pass: one block per (b,h) ----------------
__global__ void attnv_kernel() {     // grid 64, 256 threads
    int bh = blockIdx.x;
    int h = bh & 7, b = bh >> 3;
    int tid = threadIdx.x;
    int d = tid & 63, part = tid >> 6;
    __shared__ float pt[UU][256];
    __shared__ float red[256];
    float acc[UU];
    #pragma unroll
    for (int u = 0; u < UU; u++) acc[u] = 0.f;
    size_t bL = (size_t)b * LL;
    for (int kt = 0; kt < 8; kt++) {
        for (int i = tid; i < UU * 256; i += 256) {
            int u = i >> 8, c = i & 255;
            pt[u][c] = g_sc[((size_t)bh * UU + u) * LL + kt * 256 + c];
        }
        __syncthreads();
        for (int kk = part; kk < 256; kk += 4) {
            float v = g_qkv[(bL + kt * 256 + kk) * 1536 + 1024 + h * 64 + d];
            #pragma unroll
            for (int u = 0; u < UU; u++) acc[u] += pt[u][kk] * v;
        }
        __syncthreads();
    }
    #pragma unroll 1
    for (int u = 0; u < UU; u++) {
        red[tid] = acc[u]; __syncthreads();
        if (tid < 64) {
            float tot = red[tid] + red[tid + 64] + red[tid + 128] + red[tid + 192];
            g_upd[((size_t)bh * UU + u) * HD + tid] = tot / g_S[bh * UU + u];
        }
        __syncthreads();
    }
}

// ---------------- broadcast vmean into bf16 hi/lo attn buffer ----------------
__global__ void fill_kernel() {
    size_t i = (size_t)blockIdx.x * 256 + threadIdx.x;
    size_t e = i * 2;
    int d = (int)(e & 63);
    int h = (int)((e >> 6) & 7);
    int b = (int)(e >> 20);
    float v0 = g_vmean[(b * NH + h) * HD + d];
    float v1 = g_vmean[(b * NH + h) * HD + d + 1];
    __nv_bfloat16 h0 = __float2bfloat16(v0), h1 = __float2bfloat16(v1);
    *(uint32_t*)(g_aHi + e) = packbf(h0, h1);
    *(uint32_t*)(g_aLo + e) = packbf(__float2bfloat16(v0 - __bfloat162float(h0)),
                                     __float2bfloat16(v1 - __bfloat162float(h1)));
}

// ---------------- scatter updated rows (bf16 hi/lo) ----------------
__global__ void scatter_kernel() {
    int bid = blockIdx.x;
    int u = bid % UU;
    int bh = bid / UU;
    int h = bh & (NH - 1), b = bh >> 3;
    int qi = g_idxtop[bh * UU + u];
    float v = g_upd[(size_t)bid * HD + threadIdx.x];
    size_t idx = (((size_t)b * LL + qi) * NH + h) * HD + threadIdx.x;
    __nv_bfloat16 hv = __float2bfloat16(v);
    g_aHi[idx] = hv;
    g_aLo[idx] = __float2bfloat16(v - __bfloat162float(hv));
}

// ---------------- layernorm over 512 (optionally emits hi/lo) ----------------
__global__ void ln512_kernel(const float* __restrict__ in, float* __restrict__ out,
                             const float* __restrict__ g, const float* __restrict__ b,
                             size_t strideIn, size_t strideOut,
                             __nv_bfloat16* __restrict__ hiOut,
                             __nv_bfloat16* __restrict__ loOut) {
    int row = blockIdx.x;
    int tid = threadIdx.x;  // 128
    const float* x = in + (size_t)row * strideIn;
    float4 v = *(const float4*)(x + tid * 4);
    float s  = v.x + v.y + v.z + v.w;
    float ss = v.x*v.x + v.y*v.y + v.z*v.z + v.w*v.w;
    __shared__ float rs[4], rss[4];
    #pragma unroll
    for (int o = 16; o; o >>= 1) {
        s  += __shfl_xor_sync(~0u, s, o);
        ss += __shfl_xor_sync(~0u, ss, o);
    }
    int w = tid >> 5, lane = tid & 31;
    if (lane == 0) { rs[w] = s; rss[w] = ss; }
    __syncthreads();
    s  = rs[0] + rs[1] + rs[2] + rs[3];
    ss = rss[0] + rss[1] + rss[2] + rss[3];
    float m = s * (1.f / 512.f);
    float var = ss * (1.f / 512.f) - m * m;
    float r = rsqrtf(var + 1e-5f);
    float4 gg = *(const float4*)(g + tid * 4);
    float4 bb = *(const float4*)(b + tid * 4);
    float4 o4;
    o4.x = (v.x - m) * r * gg.x + bb.x;
    o4.y = (v.y - m) * r * gg.y + bb.y;
    o4.z = (v.z - m) * r * gg.z + bb.z;
    o4.w = (v.w - m) * r * gg.w + bb.w;
    *(float4*)(out + (size_t)row * strideOut + tid * 4) = o4;
    if (hiOut) {
        size_t e = (size_t)row * DMODEL + tid * 4;
        __nv_bfloat16 h0 = __float2bfloat16(o4.x), h1 = __float2bfloat16(o4.y);
        __nv_bfloat16 h2 = __float2bfloat16(o4.z), h3 = __float2bfloat16(o4.w);
        *(uint2*)(hiOut + e) = make_uint2(packbf(h0, h1), packbf(h2, h3));
        *(uint2*)(loOut + e) = make_uint2(
            packbf(__float2bfloat16(o4.x - __bfloat162float(h0)),
                   __float2bfloat16(o4.y - __bfloat162float(h1))),
            packbf(__float2bfloat16(o4.z - __bfloat162float(h2)),
                   __float2bfloat16(o4.w - __bfloat162float(h3))));
    }
}

// ---------------- final head ----------------
__global__ void head_kernel(const float* __restrict__ Wpre, const float* __restrict__ bpre,
                            const float* __restrict__ Wfc,  const float* __restrict__ bfc,
                            float* __restrict__ out) {
    int b = blockIdx.x;
    int tid = threadIdx.x;  // 256
    __shared__ float red[256];
    const float* x = g_last + (size_t)b * DMODEL;
    float acc = bpre[tid];
    const float* w = Wpre + (size_t)tid * DMODEL;
    #pragma unroll 8
    for (int k = 0; k < DMODEL; k++) acc += x[k] * w[k];
    float pre = fmaxf(acc, 0.f);
    red[tid] = pre * Wfc[tid];
    __syncthreads();
    for (int s = 128; s > 0; s >>= 1) { if (tid < s) red[tid] += red[tid + s]; __syncthreads(); }
    if (tid == 0) out[b] = red[0] + bfc[0];
}

// ---------------- host orchestration ----------------
#define SMEM_GEMM 98304

extern "C" void kernel_launch(void* const* d_in, const int* in_sizes, int n_in,
                              void* d_out, int out_size) {
    const float* x      = (const float*)d_in[0];
    const float* tfeat  = (const float*)d_in[1];
    const float* g_in   = (const float*)d_in[2];
    const float* b_in   = (const float*)d_in[3];
    const float* W_tok  = (const float*)d_in[4];
    const float* W_time = (const float*)d_in[5];
    const float* b_time = (const float*)d_in[6];
    const float* Wq     = (const float*)d_in[7];
    const float* bq     = (const float*)d_in[8];
    const float* Wk     = (const float*)d_in[9];
    const float* bk     = (const float*)d_in[10];
    const float* Wv     = (const float*)d_in[11];
    const float* bv     = (const float*)d_in[12];
    const float* Wo     = (const float*)d_in[13];
    const float* bo     = (const float*)d_in[14];
    const float* W1     = (const float*)d_in[15];
    const float* b1     = (const float*)d_in[16];
    const float* W2     = (const float*)d_in[17];
    const float* b2     = (const float*)d_in[18];
    const float* g1     = (const float*)d_in[19];
    const float* be1    = (const float*)d_in[20];
    const float* g2     = (const float*)d_in[21];
    const float* be2    = (const float*)d_in[22];
    const float* g_enc  = (const float*)d_in[23];
    const float* b_enc  = (const float*)d_in[24];
    const float* W_pre  = (const float*)d_in[25];
    const float* b_pre  = (const float*)d_in[26];
    const float* W_fc   = (const float*)d_in[27];
    const float* b_fc   = (const float*)d_in[28];

    float *h, *qkv, *last;
    __nv_bfloat16 *aHi, *aLo, *fHi, *fLo, *wbHi, *wbLo;
    cudaGetSymbolAddress((void**)&h,    g_h);
    cudaGetSymbolAddress((void**)&qkv,  g_qkv);
    cudaGetSymbolAddress((void**)&last, g_last);
    cudaGetSymbolAddress((void**)&aHi,  g_aHi);
    cudaGetSymbolAddress((void**)&aLo,  g_aLo);
    cudaGetSymbolAddress((void**)&fHi,  g_fHi);
    cudaGetSymbolAddress((void**)&fLo,  g_fLo);
    cudaGetSymbolAddress((void**)&wbHi, g_wbHi);
    cudaGetSymbolAddress((void**)&wbLo, g_wbLo);

    cudaFuncSetAttribute(tgemm_kernel<0,0,0,1>, cudaFuncAttributeMaxDynamicSharedMemorySize, SMEM_GEMM);
    cudaFuncSetAttribute(tgemm_kernel<1,0,1,0>, cudaFuncAttributeMaxDynamicSharedMemorySize, SMEM_GEMM);
    cudaFuncSetAttribute(tgemm_kernel<0,1,0,0>, cudaFuncAttributeMaxDynamicSharedMemorySize, SMEM_GEMM);

    pe_kernel<<<256, 256>>>();
    ln32_kernel<<<MROWS / 8, 256>>>(x, g_in, b_in);
    embed_kernel<<<MROWS, 128>>>(tfeat, W_tok, W_time, b_time);
    wconv_kernel<<<WTOT_F4 / 256, 256>>>((const float4*)Wq, (const float4*)Wk,
                                         (const float4*)Wv, (const float4*)Wo,
                                         (const float4*)W1, (const float4*)W2);

    dim3 gQKV(1536 / 128, MROWS / 128);
    dim3 gO(DMODEL / 128, MROWS / 128);
    dim3 gF1(DFF / 128,  MROWS / 128);
    dim3 gF2(DMODEL / 128, MROWS / 128);

    for (int i = 0; i < NE; i++) {
        size_t bOff  = (size_t)i * DMODEL;
        size_t b1Off = (size_t)i * DFF;
        size_t qkvW  = (size_t)i * QKV_PER_LAYER;
        size_t woW   = WO_OFF + (size_t)i * DMODEL * DMODEL;
        size_t w1W   = W1_OFF + (size_t)i * DFF * DMODEL;
        size_t w2W   = W2_OFF + (size_t)i * DFF * DMODEL;

        sample_kernel<<<(LL * UU + 255) / 256, 256>>>(i);

        tgemm_kernel<0,0,0,1><<<gQKV, 256, SMEM_GEMM>>>(
            aHi, aLo, wbHi + qkvW, wbLo + qkvW,
            bq + bOff, bk + bOff, bv + bOff, nullptr, qkv, nullptr, nullptr,
            MROWS, 1536, DMODEL);

        mscore_kernel<<<(BB * NH * LL * 32) / 256, 256>>>();
        topk_kernel<<<BB * NH, 256>>>();
        vmean_kernel<<<BB * NH, 256>>>();
        qkscore_kernel<<<dim3(BB * NH, 8), 256>>>();
        softmax_kernel<<<BB * NH * UU, 256>>>();
        attnv_kernel<<<BB * NH, 256>>>();
        fill_kernel<<<(MROWS * DMODEL / 2) / 256, 256>>>();
        scatter_kernel<<<BB * NH * UU, HD>>>();

        tgemm_kernel<0,1,0,0><<<gO, 256, SMEM_GEMM>>>(
            aHi, aLo, wbHi + woW, wbLo + woW,
            bo + bOff, nullptr, nullptr, h, h, nullptr, nullptr,
            MROWS, DMODEL, DMODEL);
        ln512_kernel<<<MROWS, 128>>>(h, h, g1 + bOff, be1 + bOff, DMODEL, DMODEL, aHi, aLo);

        tgemm_kernel<1,0,1,0><<<gF1, 256, SMEM_GEMM>>>(
            aHi, aLo, wbHi + w1W, wbLo + w1W,
            b1 + b1Off, nullptr, nullptr, nullptr, nullptr, fHi, fLo,
            MROWS, DFF, DMODEL);
        tgemm_kernel<0,1,0,0><<<gF2, 256, SMEM_GEMM>>>(
            fHi, fLo, wbHi + w2W, wbLo + w2W,
            b2 + bOff, nullptr, nullptr, h, h, nullptr, nullptr,
            MROWS, DMODEL, DFF);
        ln512_kernel<<<MROWS, 128>>>(h, h, g2 + bOff, be2 + bOff, DMODEL, DMODEL, aHi, aLo);
    }

    ln512_kernel<<<BB, 128>>>(h + (size_t)(LL - 1) * DMODEL, last, g_enc, b_enc,
                              (size_t)LL * DMODEL, DMODEL, nullptr, nullptr);
    head_kernel<<<BB, 256>>>(W_pre, b_pre, W_fc, b_fc, (float*)d_out);
}